// round 10
// baseline (speedup 1.0000x reference)
#include <cuda_runtime.h>
#include <cuda_fp16.h>
#include <math.h>
#include <cstdint>

#define BATCH 32
#define TLEN  512
#define DDIM  512
#define PNUM  200
#define NPS   8
#define MDIM  (BATCH*TLEN)   // 16384
#define NDIM  (PNUM*NPS)     // 1600
#define NPAD  1664           // 26 * 64 (GEMM N padding; pad cols never stored)
#define NEGC  (-100000.0f)
#define SCALE 2048.0f        // 2^11 operand prescale (keeps fp16 residuals normal)
#define INVSC (1.0f/(SCALE*SCALE))   // 2^-22, exact

// ---- scratch (static device globals; allocation-free per harness rules) ----
__device__ float g_dist[(size_t)BATCH * PNUM * TLEN * NPS];   // [bp][t*8+i], 105 MB
__device__ float4 g_part[(size_t)BATCH * PNUM * 4];           // per-quarter argmax partials
__device__ __half g_Ah[(size_t)MDIM * DDIM];                  // 16 MB
__device__ __half g_Al[(size_t)MDIM * DDIM];                  // 16 MB
__device__ __half g_Bh[(size_t)NPAD * DDIM];                  // 1.6 MB
__device__ __half g_Bl[(size_t)NPAD * DDIM];                  // 1.6 MB

// ---------------------------------------------------------------------------
// Kernel 1: normalize x rows, fp16 2-way split (x2048) -> g_Ah, g_Al
// ---------------------------------------------------------------------------
__global__ void split_x_kernel(const float* __restrict__ x) {
    int m = blockIdx.x;
    int t = threadIdx.x;           // 128 threads, 4 elems each
    const float4* row = (const float4*)(x + (size_t)m * DDIM);
    float4 v = row[t];
    float s = v.x*v.x + v.y*v.y + v.z*v.z + v.w*v.w;
    #pragma unroll
    for (int o = 16; o; o >>= 1) s += __shfl_down_sync(0xffffffffu, s, o);
    __shared__ float ws[4];
    __shared__ float sinv;
    if ((t & 31) == 0) ws[t >> 5] = s;
    __syncthreads();
    if (t == 0) sinv = 1.0f / fmaxf(sqrtf(ws[0] + ws[1] + ws[2] + ws[3]), 1e-12f);
    __syncthreads();
    float inv = sinv * SCALE;
    float xv[4] = {v.x * inv, v.y * inv, v.z * inv, v.w * inv};
    __half h[4], l[4];
    #pragma unroll
    for (int j = 0; j < 4; j++) {
        h[j] = __float2half(xv[j]);
        float r = xv[j] - __half2float(h[j]);
        l[j] = __float2half(r);
    }
    size_t off = (size_t)m * DDIM + 4 * t;
    *(__half2*)(g_Ah + off)     = __half2(h[0], h[1]);
    *(__half2*)(g_Ah + off + 2) = __half2(h[2], h[3]);
    *(__half2*)(g_Al + off)     = __half2(l[0], l[1]);
    *(__half2*)(g_Al + off + 2) = __half2(l[2], l[3]);
}

// ---------------------------------------------------------------------------
// Kernel 2: normalize prototypes, fp16 split (x2048) -> g_Bh, g_Bl [n][512].
// Pad rows (n >= 1600) zeroed.
// ---------------------------------------------------------------------------
__global__ void split_proto_kernel(const float* __restrict__ proto) {
    int p = blockIdx.x;
    int tid = (int)threadIdx.x;
    if (p >= PNUM) {   // zero pad rows
        size_t base = (size_t)p * NPS * DDIM;
        __half2 z(__half(0.f), __half(0.f));
        for (int idx = tid; idx < NPS * DDIM / 2; idx += 256) {
            ((__half2*)(g_Bh + base))[idx] = z;
            ((__half2*)(g_Bl + base))[idx] = z;
        }
        return;
    }
    __shared__ float sp[DDIM * NPS];   // 16 KB
    __shared__ float sinv[NPS];
    const float* base = proto + (size_t)p * DDIM * NPS;
    for (int idx = tid; idx < DDIM * NPS; idx += 256) sp[idx] = base[idx];
    __syncthreads();
    int w = tid >> 5, lane = tid & 31;
    if (w < NPS) {
        float s = 0.0f;
        for (int d = lane; d < DDIM; d += 32) { float v = sp[d*NPS + w]; s += v*v; }
        #pragma unroll
        for (int o = 16; o; o >>= 1) s += __shfl_down_sync(0xffffffffu, s, o);
        if (lane == 0) sinv[w] = 1.0f / fmaxf(sqrtf(s), 1e-12f);
    }
    __syncthreads();
    for (int idx = tid; idx < NPS * DDIM; idx += 256) {
        int i = idx >> 9, d = idx & (DDIM - 1);
        float v = sp[d * NPS + i] * sinv[i] * SCALE;
        __half h = __float2half(v);
        float r = v - __half2float(h);
        __half l = __float2half(r);
        size_t off = (size_t)(p * NPS + i) * DDIM + d;
        g_Bh[off] = h;
        g_Bl[off] = l;
    }
}

// ---------------------------------------------------------------------------
// Kernel 3: fp16 GEMM via mma.sync, 3 combos (hh, hl, lh), CTA 128x64,
// BK=32, 4-stage cp.async ring (96 KB smem -> 2 CTAs/SM). Epilogue emits
// per-(b,p) per-m-quarter argmax partials (raw + quantized fl(v+NEG)).
// ---------------------------------------------------------------------------
#define BM 128
#define BN 64
#define BK 32
#define KITERS (DDIM / BK)            // 16
#define A_BUF (BM * BK * 2)           // 8192
#define B_BUF (BN * BK * 2)           // 4096
#define STAGE_BYTES (2 * A_BUF + 2 * B_BUF)   // 24576
#define NSTAGE 4
#define GEMM_SMEM (NSTAGE * STAGE_BYTES)      // 98304

__device__ __forceinline__ uint32_t smem_to_u32(const void* p) {
    uint32_t a;
    asm("{ .reg .u64 t; cvta.to.shared.u64 t, %1; cvt.u32.u64 %0, t; }"
        : "=r"(a) : "l"(p));
    return a;
}
#define CP_ASYNC16(saddr, gptr) \
    asm volatile("cp.async.cg.shared.global [%0], [%1], 16;" \
        :: "r"((uint32_t)(saddr)), "l"(gptr))
#define CP_COMMIT() asm volatile("cp.async.commit_group;" ::: "memory")
#define CP_WAIT(n)  asm volatile("cp.async.wait_group %0;" :: "n"(n) : "memory")

// 64B-row swizzle: chunk ch (16B) of row -> conflict-free for 8-row ldmatrix
__device__ __forceinline__ uint32_t swz64(int row, int ch) {
    return (uint32_t)(row * 64 + ((ch ^ ((row >> 1) & 3)) << 4));
}

__device__ __forceinline__ void ldsm_x4(uint32_t (&r)[4], uint32_t addr) {
    asm volatile("ldmatrix.sync.aligned.m8n8.x4.shared.b16 {%0,%1,%2,%3}, [%4];"
        : "=r"(r[0]), "=r"(r[1]), "=r"(r[2]), "=r"(r[3]) : "r"(addr));
}
__device__ __forceinline__ void mma16816(float (&d)[4], const uint32_t (&a)[4],
                                         uint32_t b0, uint32_t b1) {
    asm volatile(
        "mma.sync.aligned.m16n8k16.row.col.f32.f16.f16.f32 "
        "{%0,%1,%2,%3}, {%4,%5,%6,%7}, {%8,%9}, {%0,%1,%2,%3};"
        : "+f"(d[0]), "+f"(d[1]), "+f"(d[2]), "+f"(d[3])
        : "r"(a[0]), "r"(a[1]), "r"(a[2]), "r"(a[3]), "r"(b0), "r"(b1));
}
__device__ __forceinline__ void amax_upd(float& bv, int& bk, float v, int k) {
    if (v > bv || (v == bv && k < bk)) { bv = v; bk = k; }
}

__global__ void __launch_bounds__(256, 2)
gemm_mma_kernel(const float* __restrict__ tmask) {
    extern __shared__ __align__(128) char smem[];
    uint32_t sb = smem_to_u32(smem);

    int tid = (int)threadIdx.x;
    int wid = tid >> 5, lane = tid & 31;
    int bm = blockIdx.y * BM, bn = blockIdx.x * BN;
    int wm = (wid >> 2) * 64;       // warp m offset: 0 / 64
    int wn = (wid & 3) * 16;        // warp n offset: 0/16/32/48

    const __half* gA[2] = {g_Ah + (size_t)bm * DDIM, g_Al + (size_t)bm * DDIM};
    const __half* gB[2] = {g_Bh + (size_t)bn * DDIM, g_Bl + (size_t)bn * DDIM};

    auto load_stage = [&](int kc, int s) {
        uint32_t st = sb + (uint32_t)s * STAGE_BYTES;
        #pragma unroll
        for (int w = 0; w < 2; w++) {        // Ah, Al: 512 chunks each
            const __half* g = gA[w] + kc * BK;
            uint32_t sbase = st + (uint32_t)w * A_BUF;
            #pragma unroll
            for (int q = 0; q < 2; q++) {
                int idx = tid + q * 256;
                int row = idx >> 2, ch = idx & 3;
                CP_ASYNC16(sbase + swz64(row, ch), g + (size_t)row * DDIM + ch * 8);
            }
        }
        #pragma unroll
        for (int w = 0; w < 2; w++) {        // Bh, Bl: 256 chunks each
            const __half* g = gB[w] + kc * BK;
            uint32_t sbase = st + 2 * A_BUF + (uint32_t)w * B_BUF;
            int row = tid >> 2, ch = tid & 3;
            CP_ASYNC16(sbase + swz64(row, ch), g + (size_t)row * DDIM + ch * 8);
        }
    };

    float d[4][2][4];
    #pragma unroll
    for (int i = 0; i < 4; i++)
        #pragma unroll
        for (int j = 0; j < 2; j++)
            #pragma unroll
            for (int q = 0; q < 4; q++) d[i][j][q] = 0.0f;

    load_stage(0, 0); CP_COMMIT();
    load_stage(1, 1); CP_COMMIT();
    load_stage(2, 2); CP_COMMIT();
    load_stage(3, 3); CP_COMMIT();

    int s = 0;
    for (int kc = 0; kc < KITERS; kc++) {
        CP_WAIT(3);
        __syncthreads();
        uint32_t st = sb + (uint32_t)s * STAGE_BYTES;
        uint32_t aHb = st, aLb = st + A_BUF;
        uint32_t bHb = st + 2 * A_BUF, bLb = bHb + B_BUF;
        #pragma unroll
        for (int ks = 0; ks < 2; ks++) {
            uint32_t ah[4][4], al[4][4];
            #pragma unroll
            for (int fm = 0; fm < 4; fm++) {
                int r = wm + fm * 16 + (lane & 15);
                int c = ks * 2 + (lane >> 4);
                uint32_t so = swz64(r, c);
                ldsm_x4(ah[fm], aHb + so);
                ldsm_x4(al[fm], aLb + so);
            }
            uint32_t bh[4], bl[4];
            {
                int r = wn + (lane & 7) + ((lane >> 4) << 3);
                int c = ks * 2 + ((lane >> 3) & 1);
                uint32_t so = swz64(r, c);
                ldsm_x4(bh, bHb + so);
                ldsm_x4(bl, bLb + so);
            }
            #pragma unroll
            for (int fm = 0; fm < 4; fm++)
                #pragma unroll
                for (int fn = 0; fn < 2; fn++) {
                    mma16816(d[fm][fn], ah[fm], bh[fn * 2], bh[fn * 2 + 1]);  // hh
                    mma16816(d[fm][fn], ah[fm], bl[fn * 2], bl[fn * 2 + 1]);  // hl
                    mma16816(d[fm][fn], al[fm], bh[fn * 2], bh[fn * 2 + 1]);  // lh
                }
        }
        __syncthreads();
        if (kc + NSTAGE < KITERS) load_stage(kc + NSTAGE, s);
        CP_COMMIT();   // empty groups at the tail keep wait-depth constant
        s = (s + 1) & (NSTAGE - 1);
    }

    // ---- epilogue: store dist + per-fn (= per-p) argmax partials ----
    int gid = lane >> 2, tig = lane & 3;
    float pv[2], pqv[2]; int pk[2], pqk[2];
    #pragma unroll
    for (int fn = 0; fn < 2; fn++) {
        pv[fn] = -INFINITY; pqv[fn] = -INFINITY;
        pk[fn] = 0x7fffffff; pqk[fn] = 0x7fffffff;
    }

    #pragma unroll
    for (int fm = 0; fm < 4; fm++) {
        int m0 = bm + wm + fm * 16 + gid;
        int m1 = m0 + 8;
        int b = m0 >> 9;              // same for m0, m1
        int t0 = m0 & (TLEN - 1), t1 = m1 & (TLEN - 1);
        float tm0 = tmask[m0], tm1 = tmask[m1];
        float s0 = INVSC * tm0, s1 = INVSC * tm1;
        float na0 = (1.0f - tm0) * NEGC, na1 = (1.0f - tm1) * NEGC;
        #pragma unroll
        for (int fn = 0; fn < 2; fn++) {
            int n = bn + wn + fn * 8 + tig * 2;
            if (n >= NDIM) continue;
            int p = n >> 3, i = n & 7;
            size_t base = ((size_t)(b * PNUM + p) << 12);
            float2 o0, o1;
            o0.x = d[fm][fn][0] * s0 + na0;
            o0.y = d[fm][fn][1] * s0 + na0;
            o1.x = d[fm][fn][2] * s1 + na1;
            o1.y = d[fm][fn][3] * s1 + na1;
            *(float2*)(g_dist + base + (t0 << 3) + i) = o0;
            *(float2*)(g_dist + base + (t1 << 3) + i) = o1;
            int k00 = (i << 9) | t0, k01 = ((i + 1) << 9) | t0;
            int k10 = (i << 9) | t1, k11 = ((i + 1) << 9) | t1;
            amax_upd(pv[fn], pk[fn], o0.x, k00);
            amax_upd(pv[fn], pk[fn], o0.y, k01);
            amax_upd(pv[fn], pk[fn], o1.x, k10);
            amax_upd(pv[fn], pk[fn], o1.y, k11);
            amax_upd(pqv[fn], pqk[fn], o0.x + NEGC, k00);
            amax_upd(pqv[fn], pqk[fn], o0.y + NEGC, k01);
            amax_upd(pqv[fn], pqk[fn], o1.x + NEGC, k10);
            amax_upd(pqv[fn], pqk[fn], o1.y + NEGC, k11);
        }
    }

    float4* sm_part = (float4*)smem;   // 16 entries, reuses stage buffers
    #pragma unroll
    for (int fn = 0; fn < 2; fn++) {
        float v = pv[fn], qv = pqv[fn];
        int k = pk[fn], qk = pqk[fn];
        #pragma unroll
        for (int o = 16; o; o >>= 1) {
            float ov = __shfl_xor_sync(0xffffffffu, v, o);
            int   ok = __shfl_xor_sync(0xffffffffu, k, o);
            amax_upd(v, k, ov, ok);
            float oqv = __shfl_xor_sync(0xffffffffu, qv, o);
            int   oqk = __shfl_xor_sync(0xffffffffu, qk, o);
            amax_upd(qv, qk, oqv, oqk);
        }
        if (lane == 0)
            sm_part[wid * 2 + fn] =
                make_float4(v, __int_as_float(k), qv, __int_as_float(qk));
    }
    __syncthreads();
    if (tid < 8) {
        int wn_i = tid >> 1, fn = tid & 1;
        float4 a = sm_part[wn_i * 2 + fn];          // warp row 0 (wm=0)
        float4 c = sm_part[(4 + wn_i) * 2 + fn];    // warp row 1 (wm=64)
        float v = a.x; int k = __float_as_int(a.y);
        float qv = a.z; int qk = __float_as_int(a.w);
        amax_upd(v, k, c.x, __float_as_int(c.y));
        amax_upd(qv, qk, c.z, __float_as_int(c.w));
        int n0 = bn + wn_i * 16 + fn * 8;
        int p = n0 >> 3;
        if (p < PNUM) {
            int b = bm >> 9;
            int quarter = (bm >> 7) & 3;
            g_part[(size_t)(b * PNUM + p) * 4 + quarter] =
                make_float4(v, __int_as_float(k), qv, __int_as_float(qk));
        }
    }
}

// ---------------------------------------------------------------------------
// Kernel 4: selection — one warp per (b,p). Combine 4 partials for it-0
// (raw) + fallback (quantized), then 7 windowed iterations reading <=56
// values each straight from g_dist. Same semantics as the proven select.
// ---------------------------------------------------------------------------
__global__ void __launch_bounds__(256)
select_kernel(const float* __restrict__ ps, float* __restrict__ out) {
    int tid = (int)threadIdx.x;
    int wid = tid >> 5, lane = tid & 31;
    int bp = blockIdx.x * 8 + wid;
    int p = bp % PNUM;
    const float* gd = g_dist + ((size_t)bp << 12);

    float fv = -INFINITY, fqv = -INFINITY;
    int fk = 0x7fffffff, fqk = 0x7fffffff;
    if (lane < 4) {
        float4 pr = g_part[(size_t)bp * 4 + lane];
        fv = pr.x; fk = __float_as_int(pr.y);
        fqv = pr.z; fqk = __float_as_int(pr.w);
    }
    #pragma unroll
    for (int o = 2; o; o >>= 1) {
        float ov = __shfl_xor_sync(0xffffffffu, fv, o);
        int   ok = __shfl_xor_sync(0xffffffffu, fk, o);
        amax_upd(fv, fk, ov, ok);
        float oqv = __shfl_xor_sync(0xffffffffu, fqv, o);
        int   oqk = __shfl_xor_sync(0xffffffffu, fqk, o);
        amax_upd(fqv, fqk, oqv, oqk);
    }
    fv  = __shfl_sync(0xffffffffu, fv, 0);
    fk  = __shfl_sync(0xffffffffu, fk, 0);
    fqv = __shfl_sync(0xffffffffu, fqv, 0);
    fqk = __shfl_sync(0xffffffffu, fqk, 0);

    float rv[NPS]; int re[NPS], rs[NPS];
    rv[0] = fv; re[0] = fk & (TLEN - 1); rs[0] = fk >> 9;
    int msub = 0xFF & ~(1 << rs[0]);
    int pe = re[0];

    #pragma unroll
    for (int it = 1; it < NPS; it++) {
        int wlo = (it == 1) ? max(pe - 3, 0) : (pe + 1);
        int whi = min(pe + 3, TLEN - 1);
        int cnt = (whi >= wlo) ? (whi - wlo + 1) * NPS : 0;
        float bv = -INFINITY;
        int   bk = 0x7fffffff;
        #pragma unroll
        for (int qq = 0; qq < 2; qq++) {
            int q = lane + qq * 32;
            if (q < cnt) {
                int t = wlo + (q >> 3), i = q & 7;
                bool ok2 = (msub >> i) & 1;
                #pragma unroll
                for (int j = 0; j < NPS - 1; j++)
                    if (j < it && re[j] == t) ok2 = false;
                if (ok2) {
                    float v = gd[(t << 3) + i];
                    amax_upd(bv, bk, v, (i << 9) | t);
                }
            }
        }
        #pragma unroll
        for (int o = 16; o; o >>= 1) {
            float ov = __shfl_xor_sync(0xffffffffu, bv, o);
            int   ok = __shfl_xor_sync(0xffffffffu, bk, o);
            amax_upd(bv, bk, ov, ok);
        }
        float recv;
        if (bk == 0x7fffffff) { bk = fqk; recv = fqv; }
        else                  recv = bv;
        int tt = bk & (TLEN - 1), ii = bk >> 9;
        rv[it] = recv; re[it] = tt; rs[it] = ii;
        msub &= ~(1 << ii);
        pe = tt;
    }

    if (lane == 0) {
        int ord[NPS];
        #pragma unroll
        for (int j = 0; j < NPS; j++) ord[j] = j;
        for (int a = 1; a < NPS; a++) {
            int o = ord[a], key = rs[o], bb = a - 1;
            while (bb >= 0 && rs[ord[bb]] > key) { ord[bb + 1] = ord[bb]; bb--; }
            ord[bb + 1] = o;
        }
        const float* pp = ps + (size_t)p * NPS;
        float slots[NPS];
        float factor = 0.0f;
        #pragma unroll
        for (int j = 0; j < NPS; j++) {
            float s = 1.0f / (1.0f + expf(-pp[j]));
            slots[j] = s; factor += s;
        }
        factor += 1e-10f;
        float acc = 0.0f;
        #pragma unroll
        for (int j = 0; j < NPS; j++)
            acc += rv[ord[j]] * (slots[j] * (float)NPS / factor);
        out[bp] = acc;
        out[BATCH * PNUM + bp] = (float)NPS - acc;
        #pragma unroll
        for (int j = 0; j < NPS; j++)
            out[2 * BATCH * PNUM + bp * NPS + j] = (float)re[ord[j]];
    }
}

// ---------------------------------------------------------------------------
extern "C" void kernel_launch(void* const* d_in, const int* in_sizes, int n_in,
                              void* d_out, int out_size) {
    (void)in_sizes; (void)n_in; (void)out_size;
    const float* x     = (const float*)d_in[0];
    const float* tmask = (const float*)d_in[1];
    const float* proto = (const float*)d_in[2];
    const float* psel  = (const float*)d_in[3];
    float* out = (float*)d_out;

    cudaFuncSetAttribute(gemm_mma_kernel,
                         cudaFuncAttributeMaxDynamicSharedMemorySize, GEMM_SMEM);

    split_x_kernel<<<MDIM, 128>>>(x);
    split_proto_kernel<<<NPAD / NPS, 256>>>(proto);
    gemm_mma_kernel<<<dim3(NPAD / BN, MDIM / BM), 256, GEMM_SMEM>>>(tmask);
    select_kernel<<<BATCH * PNUM / 8, 256>>>(psel, out);
}

// round 11
// speedup vs baseline: 1.0913x; 1.0913x over previous
#include <cuda_runtime.h>
#include <cuda_fp16.h>
#include <math.h>
#include <cstdint>

#define BATCH 32
#define TLEN  512
#define DDIM  512
#define PNUM  200
#define NPS   8
#define MDIM  (BATCH*TLEN)   // 16384
#define NDIM  (PNUM*NPS)     // 1600
#define NPAD  1664           // 13 * 128 (GEMM N padding; pad cols never stored)
#define NEGC  (-100000.0f)
#define SCALE 2048.0f        // 2^11 operand prescale (keeps fp16 residuals normal)
#define INVSC (1.0f/(SCALE*SCALE))   // 2^-22, exact

// ---- scratch (static device globals; allocation-free per harness rules) ----
__device__ float g_dist[(size_t)BATCH * PNUM * TLEN * NPS];   // [bp][t*8+i], 105 MB
__device__ float4 g_part[(size_t)BATCH * PNUM * 4];           // per-quarter argmax partials
__device__ __half g_Ah[(size_t)MDIM * DDIM];                  // 16 MB
__device__ __half g_Al[(size_t)MDIM * DDIM];                  // 16 MB
__device__ __half g_Bh[(size_t)NPAD * DDIM];                  // 1.6 MB
__device__ __half g_Bl[(size_t)NPAD * DDIM];                  // 1.6 MB

// ---------------------------------------------------------------------------
// Kernel 1: normalize x rows, fp16 2-way split (x2048) -> g_Ah, g_Al
// ---------------------------------------------------------------------------
__global__ void split_x_kernel(const float* __restrict__ x) {
    int m = blockIdx.x;
    int t = threadIdx.x;           // 128 threads, 4 elems each
    const float4* row = (const float4*)(x + (size_t)m * DDIM);
    float4 v = row[t];
    float s = v.x*v.x + v.y*v.y + v.z*v.z + v.w*v.w;
    #pragma unroll
    for (int o = 16; o; o >>= 1) s += __shfl_down_sync(0xffffffffu, s, o);
    __shared__ float ws[4];
    __shared__ float sinv;
    if ((t & 31) == 0) ws[t >> 5] = s;
    __syncthreads();
    if (t == 0) sinv = 1.0f / fmaxf(sqrtf(ws[0] + ws[1] + ws[2] + ws[3]), 1e-12f);
    __syncthreads();
    float inv = sinv * SCALE;
    float xv[4] = {v.x * inv, v.y * inv, v.z * inv, v.w * inv};
    __half h[4], l[4];
    #pragma unroll
    for (int j = 0; j < 4; j++) {
        h[j] = __float2half(xv[j]);
        float r = xv[j] - __half2float(h[j]);
        l[j] = __float2half(r);
    }
    size_t off = (size_t)m * DDIM + 4 * t;
    *(__half2*)(g_Ah + off)     = __half2(h[0], h[1]);
    *(__half2*)(g_Ah + off + 2) = __half2(h[2], h[3]);
    *(__half2*)(g_Al + off)     = __half2(l[0], l[1]);
    *(__half2*)(g_Al + off + 2) = __half2(l[2], l[3]);
}

// ---------------------------------------------------------------------------
// Kernel 2: normalize prototypes, fp16 split (x2048) -> g_Bh, g_Bl [n][512].
// Pad rows (n >= 1600) zeroed.
// ---------------------------------------------------------------------------
__global__ void split_proto_kernel(const float* __restrict__ proto) {
    int p = blockIdx.x;
    int tid = (int)threadIdx.x;
    if (p >= PNUM) {   // zero pad rows
        size_t base = (size_t)p * NPS * DDIM;
        __half2 z(__half(0.f), __half(0.f));
        for (int idx = tid; idx < NPS * DDIM / 2; idx += 256) {
            ((__half2*)(g_Bh + base))[idx] = z;
            ((__half2*)(g_Bl + base))[idx] = z;
        }
        return;
    }
    __shared__ float sp[DDIM * NPS];   // 16 KB
    __shared__ float sinv[NPS];
    const float* base = proto + (size_t)p * DDIM * NPS;
    for (int idx = tid; idx < DDIM * NPS; idx += 256) sp[idx] = base[idx];
    __syncthreads();
    int w = tid >> 5, lane = tid & 31;
    if (w < NPS) {
        float s = 0.0f;
        for (int d = lane; d < DDIM; d += 32) { float v = sp[d*NPS + w]; s += v*v; }
        #pragma unroll
        for (int o = 16; o; o >>= 1) s += __shfl_down_sync(0xffffffffu, s, o);
        if (lane == 0) sinv[w] = 1.0f / fmaxf(sqrtf(s), 1e-12f);
    }
    __syncthreads();
    for (int idx = tid; idx < NPS * DDIM; idx += 256) {
        int i = idx >> 9, d = idx & (DDIM - 1);
        float v = sp[d * NPS + i] * sinv[i] * SCALE;
        __half h = __float2half(v);
        float r = v - __half2float(h);
        __half l = __float2half(r);
        size_t off = (size_t)(p * NPS + i) * DDIM + d;
        g_Bh[off] = h;
        g_Bl[off] = l;
    }
}

// ---------------------------------------------------------------------------
// Kernel 3: fp16 GEMM via mma.sync, 3 combos (hh, hl, lh). CTA 128x128
// (warp tile 64x32 — R9's proven compute shape), BK=32, 3-stage ring:
// 96 KB smem -> 2 CTAs/SM (the occupancy R10 aimed for, without shrinking
// the tile). Epilogue emits per-(b,p) per-m-quarter argmax partials.
// ---------------------------------------------------------------------------
#define BM 128
#define BN 128
#define BK 32
#define KITERS (DDIM / BK)            // 16
#define BUF_BYTES (BM * BK * 2)       // 8192 per buffer
#define NSTAGE 3
#define GEMM_SMEM (NSTAGE * 4 * BUF_BYTES)  // 98304

__device__ __forceinline__ uint32_t smem_to_u32(const void* p) {
    uint32_t a;
    asm("{ .reg .u64 t; cvta.to.shared.u64 t, %1; cvt.u32.u64 %0, t; }"
        : "=r"(a) : "l"(p));
    return a;
}
#define CP_ASYNC16(saddr, gptr) \
    asm volatile("cp.async.cg.shared.global [%0], [%1], 16;" \
        :: "r"((uint32_t)(saddr)), "l"(gptr))
#define CP_COMMIT() asm volatile("cp.async.commit_group;" ::: "memory")
#define CP_WAIT(n)  asm volatile("cp.async.wait_group %0;" :: "n"(n) : "memory")

// 64B-row swizzle (proven in R10): conflict-free for 8-row ldmatrix access
__device__ __forceinline__ uint32_t swz64(int row, int ch) {
    return (uint32_t)(row * 64 + ((ch ^ ((row >> 1) & 3)) << 4));
}

__device__ __forceinline__ void ldsm_x4(uint32_t (&r)[4], uint32_t addr) {
    asm volatile("ldmatrix.sync.aligned.m8n8.x4.shared.b16 {%0,%1,%2,%3}, [%4];"
        : "=r"(r[0]), "=r"(r[1]), "=r"(r[2]), "=r"(r[3]) : "r"(addr));
}
__device__ __forceinline__ void mma16816(float (&d)[4], const uint32_t (&a)[4],
                                         uint32_t b0, uint32_t b1) {
    asm volatile(
        "mma.sync.aligned.m16n8k16.row.col.f32.f16.f16.f32 "
        "{%0,%1,%2,%3}, {%4,%5,%6,%7}, {%8,%9}, {%0,%1,%2,%3};"
        : "+f"(d[0]), "+f"(d[1]), "+f"(d[2]), "+f"(d[3])
        : "r"(a[0]), "r"(a[1]), "r"(a[2]), "r"(a[3]), "r"(b0), "r"(b1));
}
__device__ __forceinline__ void amax_upd(float& bv, int& bk, float v, int k) {
    if (v > bv || (v == bv && k < bk)) { bv = v; bk = k; }
}

__global__ void __launch_bounds__(256, 2)
gemm_mma_kernel(const float* __restrict__ tmask) {
    extern __shared__ __align__(128) char smem[];
    uint32_t sb = smem_to_u32(smem);

    int tid = (int)threadIdx.x;
    int wid = tid >> 5, lane = tid & 31;
    int bm = blockIdx.y * BM, bn = blockIdx.x * BN;
    int wm = (wid >> 2) * 64;       // warp m offset: 0 / 64
    int wn = (wid & 3) * 32;        // warp n offset: 0/32/64/96

    auto buf = [&](int s, int w) -> uint32_t {
        return sb + (uint32_t)(s * 4 + w) * BUF_BYTES;
    };

    const __half* gsrc[4] = {g_Ah + (size_t)bm * DDIM, g_Al + (size_t)bm * DDIM,
                             g_Bh + (size_t)bn * DDIM, g_Bl + (size_t)bn * DDIM};

    auto load_stage = [&](int kc, int s) {
        #pragma unroll
        for (int w = 0; w < 4; w++) {
            const __half* g = gsrc[w] + kc * BK;
            uint32_t sbase = buf(s, w);
            #pragma unroll
            for (int q = 0; q < 2; q++) {
                int idx = tid + q * 256;
                int row = idx >> 2, ch = idx & 3;
                CP_ASYNC16(sbase + swz64(row, ch), g + (size_t)row * DDIM + ch * 8);
            }
        }
    };

    float d[4][4][4];
    #pragma unroll
    for (int i = 0; i < 4; i++)
        #pragma unroll
        for (int j = 0; j < 4; j++)
            #pragma unroll
            for (int q = 0; q < 4; q++) d[i][j][q] = 0.0f;

    load_stage(0, 0); CP_COMMIT();
    load_stage(1, 1); CP_COMMIT();
    load_stage(2, 2); CP_COMMIT();

    int s = 0;
    for (int kc = 0; kc < KITERS; kc++) {
        CP_WAIT(2);
        __syncthreads();
        uint32_t aHb = buf(s, 0), aLb = buf(s, 1), bHb = buf(s, 2), bLb = buf(s, 3);
        #pragma unroll
        for (int ks = 0; ks < 2; ks++) {
            uint32_t ah[4][4], al[4][4];
            #pragma unroll
            for (int fm = 0; fm < 4; fm++) {
                int r = wm + fm * 16 + (lane & 15);
                int c = ks * 2 + (lane >> 4);
                uint32_t so = swz64(r, c);
                ldsm_x4(ah[fm], aHb + so);
                ldsm_x4(al[fm], aLb + so);
            }
            uint32_t bh[2][4], bl[2][4];
            #pragma unroll
            for (int g = 0; g < 2; g++) {
                int r = wn + g * 16 + (lane & 7) + ((lane >> 4) << 3);
                int c = ks * 2 + ((lane >> 3) & 1);
                uint32_t so = swz64(r, c);
                ldsm_x4(bh[g], bHb + so);
                ldsm_x4(bl[g], bLb + so);
            }
            #pragma unroll
            for (int fm = 0; fm < 4; fm++)
                #pragma unroll
                for (int fn = 0; fn < 4; fn++) {
                    uint32_t bh0 = bh[fn >> 1][(fn & 1) * 2];
                    uint32_t bh1 = bh[fn >> 1][(fn & 1) * 2 + 1];
                    uint32_t bl0 = bl[fn >> 1][(fn & 1) * 2];
                    uint32_t bl1 = bl[fn >> 1][(fn & 1) * 2 + 1];
                    mma16816(d[fm][fn], ah[fm], bh0, bh1);   // hh
                    mma16816(d[fm][fn], ah[fm], bl0, bl1);   // hl
                    mma16816(d[fm][fn], al[fm], bh0, bh1);   // lh
                }
        }
        __syncthreads();
        if (kc + NSTAGE < KITERS) load_stage(kc + NSTAGE, s);
        CP_COMMIT();   // empty groups at the tail keep wait-depth constant
        s = (s == NSTAGE - 1) ? 0 : s + 1;
    }

    // ---- epilogue: store dist + per-fn (=per-p) argmax partials ----
    int gid = lane >> 2, tig = lane & 3;
    float pv[4], pqv[4]; int pk[4], pqk[4];
    #pragma unroll
    for (int fn = 0; fn < 4; fn++) {
        pv[fn] = -INFINITY; pqv[fn] = -INFINITY;
        pk[fn] = 0x7fffffff; pqk[fn] = 0x7fffffff;
    }

    #pragma unroll
    for (int fm = 0; fm < 4; fm++) {
        int m0 = bm + wm + fm * 16 + gid;
        int m1 = m0 + 8;
        int b = m0 >> 9;              // same for m0, m1
        int t0 = m0 & (TLEN - 1), t1 = m1 & (TLEN - 1);
        float tm0 = tmask[m0], tm1 = tmask[m1];
        float s0 = INVSC * tm0, s1 = INVSC * tm1;
        float na0 = (1.0f - tm0) * NEGC, na1 = (1.0f - tm1) * NEGC;
        #pragma unroll
        for (int fn = 0; fn < 4; fn++) {
            int n = bn + wn + fn * 8 + tig * 2;
            if (n >= NDIM) continue;
            int p = n >> 3, i = n & 7;
            size_t base = ((size_t)(b * PNUM + p) << 12);
            float2 o0, o1;
            o0.x = d[fm][fn][0] * s0 + na0;
            o0.y = d[fm][fn][1] * s0 + na0;
            o1.x = d[fm][fn][2] * s1 + na1;
            o1.y = d[fm][fn][3] * s1 + na1;
            *(float2*)(g_dist + base + (t0 << 3) + i) = o0;
            *(float2*)(g_dist + base + (t1 << 3) + i) = o1;
            int k00 = (i << 9) | t0, k01 = ((i + 1) << 9) | t0;
            int k10 = (i << 9) | t1, k11 = ((i + 1) << 9) | t1;
            amax_upd(pv[fn], pk[fn], o0.x, k00);
            amax_upd(pv[fn], pk[fn], o0.y, k01);
            amax_upd(pv[fn], pk[fn], o1.x, k10);
            amax_upd(pv[fn], pk[fn], o1.y, k11);
            amax_upd(pqv[fn], pqk[fn], o0.x + NEGC, k00);
            amax_upd(pqv[fn], pqk[fn], o0.y + NEGC, k01);
            amax_upd(pqv[fn], pqk[fn], o1.x + NEGC, k10);
            amax_upd(pqv[fn], pqk[fn], o1.y + NEGC, k11);
        }
    }

    float4* sm_part = (float4*)smem;   // 32 entries, reuses stage buffers
    #pragma unroll
    for (int fn = 0; fn < 4; fn++) {
        float v = pv[fn], qv = pqv[fn];
        int k = pk[fn], qk = pqk[fn];
        #pragma unroll
        for (int o = 16; o; o >>= 1) {
            float ov = __shfl_xor_sync(0xffffffffu, v, o);
            int   ok = __shfl_xor_sync(0xffffffffu, k, o);
            amax_upd(v, k, ov, ok);
            float oqv = __shfl_xor_sync(0xffffffffu, qv, o);
            int   oqk = __shfl_xor_sync(0xffffffffu, qk, o);
            amax_upd(qv, qk, oqv, oqk);
        }
        if (lane == 0)
            sm_part[wid * 4 + fn] =
                make_float4(v, __int_as_float(k), qv, __int_as_float(qk));
    }
    __syncthreads();
    if (tid < 16) {
        int wn_i = tid >> 2, fn = tid & 3;
        float4 a = sm_part[wn_i * 4 + fn];          // warp row 0 (wm=0)
        float4 c = sm_part[(4 + wn_i) * 4 + fn];    // warp row 1 (wm=64)
        float v = a.x; int k = __float_as_int(a.y);
        float qv = a.z; int qk = __float_as_int(a.w);
        amax_upd(v, k, c.x, __float_as_int(c.y));
        amax_upd(qv, qk, c.z, __float_as_int(c.w));
        int n0 = bn + wn_i * 32 + fn * 8;
        int p = n0 >> 3;
        if (p < PNUM) {
            int b = bm >> 9;
            int quarter = (bm >> 7) & 3;
            g_part[(size_t)(b * PNUM + p) * 4 + quarter] =
                make_float4(v, __int_as_float(k), qv, __int_as_float(qk));
        }
    }
}

// ---------------------------------------------------------------------------
// Kernel 4: selection — one warp per (b,p). Combine 4 partials for it-0
// (raw) + fallback (quantized), then 7 windowed iterations reading <=56
// values each straight from g_dist. Same semantics as the proven select.
// ---------------------------------------------------------------------------
__global__ void __launch_bounds__(256)
select_kernel(const float* __restrict__ ps, float* __restrict__ out) {
    int tid = (int)threadIdx.x;
    int wid = tid >> 5, lane = tid & 31;
    int bp = blockIdx.x * 8 + wid;
    int p = bp % PNUM;
    const float* gd = g_dist + ((size_t)bp << 12);

    float fv = -INFINITY, fqv = -INFINITY;
    int fk = 0x7fffffff, fqk = 0x7fffffff;
    if (lane < 4) {
        float4 pr = g_part[(size_t)bp * 4 + lane];
        fv = pr.x; fk = __float_as_int(pr.y);
        fqv = pr.z; fqk = __float_as_int(pr.w);
    }
    #pragma unroll
    for (int o = 2; o; o >>= 1) {
        float ov = __shfl_xor_sync(0xffffffffu, fv, o);
        int   ok = __shfl_xor_sync(0xffffffffu, fk, o);
        amax_upd(fv, fk, ov, ok);
        float oqv = __shfl_xor_sync(0xffffffffu, fqv, o);
        int   oqk = __shfl_xor_sync(0xffffffffu, fqk, o);
        amax_upd(fqv, fqk, oqv, oqk);
    }
    fv  = __shfl_sync(0xffffffffu, fv, 0);
    fk  = __shfl_sync(0xffffffffu, fk, 0);
    fqv = __shfl_sync(0xffffffffu, fqv, 0);
    fqk = __shfl_sync(0xffffffffu, fqk, 0);

    float rv[NPS]; int re[NPS], rs[NPS];
    rv[0] = fv; re[0] = fk & (TLEN - 1); rs[0] = fk >> 9;
    int msub = 0xFF & ~(1 << rs[0]);
    int pe = re[0];

    #pragma unroll
    for (int it = 1; it < NPS; it++) {
        int wlo = (it == 1) ? max(pe - 3, 0) : (pe + 1);
        int whi = min(pe + 3, TLEN - 1);
        int cnt = (whi >= wlo) ? (whi - wlo + 1) * NPS : 0;
        float bv = -INFINITY;
        int   bk = 0x7fffffff;
        #pragma unroll
        for (int qq = 0; qq < 2; qq++) {
            int q = lane + qq * 32;
            if (q < cnt) {
                int t = wlo + (q >> 3), i = q & 7;
                bool ok2 = (msub >> i) & 1;
                #pragma unroll
                for (int j = 0; j < NPS - 1; j++)
                    if (j < it && re[j] == t) ok2 = false;
                if (ok2) {
                    float v = gd[(t << 3) + i];
                    amax_upd(bv, bk, v, (i << 9) | t);
                }
            }
        }
        #pragma unroll
        for (int o = 16; o; o >>= 1) {
            float ov = __shfl_xor_sync(0xffffffffu, bv, o);
            int   ok = __shfl_xor_sync(0xffffffffu, bk, o);
            amax_upd(bv, bk, ov, ok);
        }
        float recv;
        if (bk == 0x7fffffff) { bk = fqk; recv = fqv; }
        else                  recv = bv;
        int tt = bk & (TLEN - 1), ii = bk >> 9;
        rv[it] = recv; re[it] = tt; rs[it] = ii;
        msub &= ~(1 << ii);
        pe = tt;
    }

    if (lane == 0) {
        int ord[NPS];
        #pragma unroll
        for (int j = 0; j < NPS; j++) ord[j] = j;
        for (int a = 1; a < NPS; a++) {
            int o = ord[a], key = rs[o], bb = a - 1;
            while (bb >= 0 && rs[ord[bb]] > key) { ord[bb + 1] = ord[bb]; bb--; }
            ord[bb + 1] = o;
        }
        const float* pp = ps + (size_t)p * NPS;
        float slots[NPS];
        float factor = 0.0f;
        #pragma unroll
        for (int j = 0; j < NPS; j++) {
            float s = 1.0f / (1.0f + expf(-pp[j]));
            slots[j] = s; factor += s;
        }
        factor += 1e-10f;
        float acc = 0.0f;
        #pragma unroll
        for (int j = 0; j < NPS; j++)
            acc += rv[ord[j]] * (slots[j] * (float)NPS / factor);
        out[bp] = acc;
        out[BATCH * PNUM + bp] = (float)NPS - acc;
        #pragma unroll
        for (int j = 0; j < NPS; j++)
            out[2 * BATCH * PNUM + bp * NPS + j] = (float)re[ord[j]];
    }
}

// ---------------------------------------------------------------------------
extern "C" void kernel_launch(void* const* d_in, const int* in_sizes, int n_in,
                              void* d_out, int out_size) {
    (void)in_sizes; (void)n_in; (void)out_size;
    const float* x     = (const float*)d_in[0];
    const float* tmask = (const float*)d_in[1];
    const float* proto = (const float*)d_in[2];
    const float* psel  = (const float*)d_in[3];
    float* out = (float*)d_out;

    cudaFuncSetAttribute(gemm_mma_kernel,
                         cudaFuncAttributeMaxDynamicSharedMemorySize, GEMM_SMEM);

    split_x_kernel<<<MDIM, 128>>>(x);
    split_proto_kernel<<<NPAD / NPS, 256>>>(proto);
    gemm_mma_kernel<<<dim3(NPAD / BN, MDIM / BM), 256, GEMM_SMEM>>>(tmask);
    select_kernel<<<BATCH * PNUM / 8, 256>>>(psel, out);
}

// round 12
// speedup vs baseline: 1.1185x; 1.0249x over previous
#include <cuda_runtime.h>
#include <cuda_fp16.h>
#include <math.h>
#include <cstdint>

#define BATCH 32
#define TLEN  512
#define DDIM  512
#define PNUM  200
#define NPS   8
#define MDIM  (BATCH*TLEN)   // 16384
#define NDIM  (PNUM*NPS)     // 1600
#define NPAD  1664           // 13 * 128 (GEMM N padding; pad cols never stored)
#define NEGC  (-100000.0f)
#define SCALE 2048.0f        // 2^11 operand prescale (keeps fp16 residuals normal)
#define INVSC (1.0f/(SCALE*SCALE))   // 2^-22, exact

// ---- scratch (static device globals; allocation-free per harness rules) ----
__device__ float g_dist[(size_t)BATCH * PNUM * TLEN * NPS];   // [bp][t*8+i], 105 MB
__device__ float4 g_part[(size_t)BATCH * PNUM * 4];           // per-quarter argmax partials
__device__ __half g_Ah[(size_t)MDIM * DDIM];                  // 16 MB
__device__ __half g_Al[(size_t)MDIM * DDIM];                  // 16 MB
__device__ __half g_Bh[(size_t)NPAD * DDIM];                  // 1.6 MB
__device__ __half g_Bl[(size_t)NPAD * DDIM];                  // 1.6 MB

// ---------------------------------------------------------------------------
// Kernel 1 (merged): blocks [0, MDIM) split x rows; blocks [MDIM, MDIM+208)
// split prototypes (or zero pad rows). 256 threads each.
// ---------------------------------------------------------------------------
__global__ void split_all_kernel(const float* __restrict__ x,
                                 const float* __restrict__ proto) {
    int blk = blockIdx.x;
    int tid = (int)threadIdx.x;

    if (blk < MDIM) {
        // ---- x row split: 256 threads, 2 floats each ----
        int m = blk;
        const float2* row = (const float2*)(x + (size_t)m * DDIM);
        float2 v = row[tid];
        float s = v.x * v.x + v.y * v.y;
        #pragma unroll
        for (int o = 16; o; o >>= 1) s += __shfl_down_sync(0xffffffffu, s, o);
        __shared__ float ws[8];
        __shared__ float sinv;
        if ((tid & 31) == 0) ws[tid >> 5] = s;
        __syncthreads();
        if (tid == 0) {
            float t = ws[0] + ws[1] + ws[2] + ws[3] + ws[4] + ws[5] + ws[6] + ws[7];
            sinv = 1.0f / fmaxf(sqrtf(t), 1e-12f);
        }
        __syncthreads();
        float inv = sinv * SCALE;
        float x0 = v.x * inv, x1 = v.y * inv;
        __half h0 = __float2half(x0);
        __half l0 = __float2half(x0 - __half2float(h0));
        __half h1 = __float2half(x1);
        __half l1 = __float2half(x1 - __half2float(h1));
        size_t off = (size_t)m * DDIM + 2 * tid;
        *(__half2*)(g_Ah + off) = __half2(h0, h1);
        *(__half2*)(g_Al + off) = __half2(l0, l1);
        return;
    }

    // ---- prototype split ----
    int p = blk - MDIM;
    if (p >= PNUM) {   // zero pad rows
        size_t base = (size_t)p * NPS * DDIM;
        __half2 z(__half(0.f), __half(0.f));
        for (int idx = tid; idx < NPS * DDIM / 2; idx += 256) {
            ((__half2*)(g_Bh + base))[idx] = z;
            ((__half2*)(g_Bl + base))[idx] = z;
        }
        return;
    }
    __shared__ float sp[DDIM * NPS];   // 16 KB
    __shared__ float sinvp[NPS];
    const float* base = proto + (size_t)p * DDIM * NPS;
    for (int idx = tid; idx < DDIM * NPS; idx += 256) sp[idx] = base[idx];
    __syncthreads();
    int w = tid >> 5, lane = tid & 31;
    if (w < NPS) {
        float s = 0.0f;
        for (int d = lane; d < DDIM; d += 32) { float v = sp[d*NPS + w]; s += v*v; }
        #pragma unroll
        for (int o = 16; o; o >>= 1) s += __shfl_down_sync(0xffffffffu, s, o);
        if (lane == 0) sinvp[w] = 1.0f / fmaxf(sqrtf(s), 1e-12f);
    }
    __syncthreads();
    for (int idx = tid; idx < NPS * DDIM; idx += 256) {
        int i = idx >> 9, d = idx & (DDIM - 1);
        float v = sp[d * NPS + i] * sinvp[i] * SCALE;
        __half h = __float2half(v);
        float r = v - __half2float(h);
        __half l = __float2half(r);
        size_t off = (size_t)(p * NPS + i) * DDIM + d;
        g_Bh[off] = h;
        g_Bl[off] = l;
    }
}

// ---------------------------------------------------------------------------
// Kernel 2: fp16 GEMM via mma.sync, 3 combos (hh, hl, lh). CTA 128x128,
// BK=32, 3-stage ring, ONE __syncthreads per mainloop iteration.
// 96 KB smem -> 2 CTAs/SM. Epilogue emits per-(b,p) per-quarter partials.
// ---------------------------------------------------------------------------
#define BM 128
#define BN 128
#define BK 32
#define KITERS (DDIM / BK)            // 16
#define BUF_BYTES (BM * BK * 2)       // 8192 per buffer
#define NSTAGE 3
#define GEMM_SMEM (NSTAGE * 4 * BUF_BYTES)  // 98304

__device__ __forceinline__ uint32_t smem_to_u32(const void* p) {
    uint32_t a;
    asm("{ .reg .u64 t; cvta.to.shared.u64 t, %1; cvt.u32.u64 %0, t; }"
        : "=r"(a) : "l"(p));
    return a;
}
#define CP_ASYNC16(saddr, gptr) \
    asm volatile("cp.async.cg.shared.global [%0], [%1], 16;" \
        :: "r"((uint32_t)(saddr)), "l"(gptr))
#define CP_COMMIT() asm volatile("cp.async.commit_group;" ::: "memory")
#define CP_WAIT(n)  asm volatile("cp.async.wait_group %0;" :: "n"(n) : "memory")

// 64B-row swizzle: conflict-free for 8-row ldmatrix access
__device__ __forceinline__ uint32_t swz64(int row, int ch) {
    return (uint32_t)(row * 64 + ((ch ^ ((row >> 1) & 3)) << 4));
}

__device__ __forceinline__ void ldsm_x4(uint32_t (&r)[4], uint32_t addr) {
    asm volatile("ldmatrix.sync.aligned.m8n8.x4.shared.b16 {%0,%1,%2,%3}, [%4];"
        : "=r"(r[0]), "=r"(r[1]), "=r"(r[2]), "=r"(r[3]) : "r"(addr));
}
__device__ __forceinline__ void mma16816(float (&d)[4], const uint32_t (&a)[4],
                                         uint32_t b0, uint32_t b1) {
    asm volatile(
        "mma.sync.aligned.m16n8k16.row.col.f32.f16.f16.f32 "
        "{%0,%1,%2,%3}, {%4,%5,%6,%7}, {%8,%9}, {%0,%1,%2,%3};"
        : "+f"(d[0]), "+f"(d[1]), "+f"(d[2]), "+f"(d[3])
        : "r"(a[0]), "r"(a[1]), "r"(a[2]), "r"(a[3]), "r"(b0), "r"(b1));
}
__device__ __forceinline__ void amax_upd(float& bv, int& bk, float v, int k) {
    if (v > bv || (v == bv && k < bk)) { bv = v; bk = k; }
}

__global__ void __launch_bounds__(256, 2)
gemm_mma_kernel(const float* __restrict__ tmask) {
    extern __shared__ __align__(128) char smem[];
    uint32_t sb = smem_to_u32(smem);

    int tid = (int)threadIdx.x;
    int wid = tid >> 5, lane = tid & 31;
    int bm = blockIdx.y * BM, bn = blockIdx.x * BN;
    int wm = (wid >> 2) * 64;       // warp m offset: 0 / 64
    int wn = (wid & 3) * 32;        // warp n offset: 0/32/64/96

    auto buf = [&](int s, int w) -> uint32_t {
        return sb + (uint32_t)(s * 4 + w) * BUF_BYTES;
    };

    const __half* gsrc[4] = {g_Ah + (size_t)bm * DDIM, g_Al + (size_t)bm * DDIM,
                             g_Bh + (size_t)bn * DDIM, g_Bl + (size_t)bn * DDIM};

    auto load_stage = [&](int kc, int s) {
        #pragma unroll
        for (int w = 0; w < 4; w++) {
            const __half* g = gsrc[w] + kc * BK;
            uint32_t sbase = buf(s, w);
            #pragma unroll
            for (int q = 0; q < 2; q++) {
                int idx = tid + q * 256;
                int row = idx >> 2, ch = idx & 3;
                CP_ASYNC16(sbase + swz64(row, ch), g + (size_t)row * DDIM + ch * 8);
            }
        }
    };

    float d[4][4][4];
    #pragma unroll
    for (int i = 0; i < 4; i++)
        #pragma unroll
        for (int j = 0; j < 4; j++)
            #pragma unroll
            for (int q = 0; q < 4; q++) d[i][j][q] = 0.0f;

    // prologue: NSTAGE-1 stages in flight
    load_stage(0, 0); CP_COMMIT();
    load_stage(1, 1); CP_COMMIT();
    CP_WAIT(1);
    __syncthreads();

    int s = 0;
    for (int kc = 0; kc < KITERS; kc++) {
        uint32_t aHb = buf(s, 0), aLb = buf(s, 1), bHb = buf(s, 2), bLb = buf(s, 3);
        #pragma unroll
        for (int ks = 0; ks < 2; ks++) {
            uint32_t ah[4][4], al[4][4];
            #pragma unroll
            for (int fm = 0; fm < 4; fm++) {
                int r = wm + fm * 16 + (lane & 15);
                int c = ks * 2 + (lane >> 4);
                uint32_t so = swz64(r, c);
                ldsm_x4(ah[fm], aHb + so);
                ldsm_x4(al[fm], aLb + so);
            }
            uint32_t bh[2][4], bl[2][4];
            #pragma unroll
            for (int g = 0; g < 2; g++) {
                int r = wn + g * 16 + (lane & 7) + ((lane >> 4) << 3);
                int c = ks * 2 + ((lane >> 3) & 1);
                uint32_t so = swz64(r, c);
                ldsm_x4(bh[g], bHb + so);
                ldsm_x4(bl[g], bLb + so);
            }
            #pragma unroll
            for (int fm = 0; fm < 4; fm++)
                #pragma unroll
                for (int fn = 0; fn < 4; fn++) {
                    uint32_t bh0 = bh[fn >> 1][(fn & 1) * 2];
                    uint32_t bh1 = bh[fn >> 1][(fn & 1) * 2 + 1];
                    uint32_t bl0 = bl[fn >> 1][(fn & 1) * 2];
                    uint32_t bl1 = bl[fn >> 1][(fn & 1) * 2 + 1];
                    mma16816(d[fm][fn], ah[fm], bh0, bh1);   // hh
                    mma16816(d[fm][fn], ah[fm], bl0, bl1);   // hl
                    mma16816(d[fm][fn], al[fm], bh0, bh1);   // lh
                }
        }
        // load stage (kc+2): its last readers finished before the sync that
        // ended iteration kc-1, so no extra barrier is needed here.
        int nk = kc + NSTAGE - 1;
        if (nk < KITERS) load_stage(nk, nk % NSTAGE);
        CP_COMMIT();   // empty groups at the tail keep wait-depth constant
        CP_WAIT(1);    // stage for kc+1 resident
        __syncthreads();
        s = (s == NSTAGE - 1) ? 0 : s + 1;
    }

    // ---- epilogue: store dist + per-fn (=per-p) argmax partials ----
    int gid = lane >> 2, tig = lane & 3;
    float pv[4], pqv[4]; int pk[4], pqk[4];
    #pragma unroll
    for (int fn = 0; fn < 4; fn++) {
        pv[fn] = -INFINITY; pqv[fn] = -INFINITY;
        pk[fn] = 0x7fffffff; pqk[fn] = 0x7fffffff;
    }

    #pragma unroll
    for (int fm = 0; fm < 4; fm++) {
        int m0 = bm + wm + fm * 16 + gid;
        int m1 = m0 + 8;
        int b = m0 >> 9;              // same for m0, m1
        int t0 = m0 & (TLEN - 1), t1 = m1 & (TLEN - 1);
        float tm0 = tmask[m0], tm1 = tmask[m1];
        float s0 = INVSC * tm0, s1 = INVSC * tm1;
        float na0 = (1.0f - tm0) * NEGC, na1 = (1.0f - tm1) * NEGC;
        #pragma unroll
        for (int fn = 0; fn < 4; fn++) {
            int n = bn + wn + fn * 8 + tig * 2;
            if (n >= NDIM) continue;
            int p = n >> 3, i = n & 7;
            size_t base = ((size_t)(b * PNUM + p) << 12);
            float2 o0, o1;
            o0.x = d[fm][fn][0] * s0 + na0;
            o0.y = d[fm][fn][1] * s0 + na0;
            o1.x = d[fm][fn][2] * s1 + na1;
            o1.y = d[fm][fn][3] * s1 + na1;
            *(float2*)(g_dist + base + (t0 << 3) + i) = o0;
            *(float2*)(g_dist + base + (t1 << 3) + i) = o1;
            int k00 = (i << 9) | t0, k01 = ((i + 1) << 9) | t0;
            int k10 = (i << 9) | t1, k11 = ((i + 1) << 9) | t1;
            amax_upd(pv[fn], pk[fn], o0.x, k00);
            amax_upd(pv[fn], pk[fn], o0.y, k01);
            amax_upd(pv[fn], pk[fn], o1.x, k10);
            amax_upd(pv[fn], pk[fn], o1.y, k11);
            amax_upd(pqv[fn], pqk[fn], o0.x + NEGC, k00);
            amax_upd(pqv[fn], pqk[fn], o0.y + NEGC, k01);
            amax_upd(pqv[fn], pqk[fn], o1.x + NEGC, k10);
            amax_upd(pqv[fn], pqk[fn], o1.y + NEGC, k11);
        }
    }

    float4* sm_part = (float4*)smem;   // 32 entries, reuses stage buffers
    __syncthreads();                   // mainloop smem reads fully done
    #pragma unroll
    for (int fn = 0; fn < 4; fn++) {
        float v = pv[fn], qv = pqv[fn];
        int k = pk[fn], qk = pqk[fn];
        #pragma unroll
        for (int o = 16; o; o >>= 1) {
            float ov = __shfl_xor_sync(0xffffffffu, v, o);
            int   ok = __shfl_xor_sync(0xffffffffu, k, o);
            amax_upd(v, k, ov, ok);
            float oqv = __shfl_xor_sync(0xffffffffu, qv, o);
            int   oqk = __shfl_xor_sync(0xffffffffu, qk, o);
            amax_upd(qv, qk, oqv, oqk);
        }
        if (lane == 0)
            sm_part[wid * 4 + fn] =
                make_float4(v, __int_as_float(k), qv, __int_as_float(qk));
    }
    __syncthreads();
    if (tid < 16) {
        int wn_i = tid >> 2, fn = tid & 3;
        float4 a = sm_part[wn_i * 4 + fn];          // warp row 0 (wm=0)
        float4 c = sm_part[(4 + wn_i) * 4 + fn];    // warp row 1 (wm=64)
        float v = a.x; int k = __float_as_int(a.y);
        float qv = a.z; int qk = __float_as_int(a.w);
        amax_upd(v, k, c.x, __float_as_int(c.y));
        amax_upd(qv, qk, c.z, __float_as_int(c.w));
        int n0 = bn + wn_i * 32 + fn * 8;
        int p = n0 >> 3;
        if (p < PNUM) {
            int b = bm >> 9;
            int quarter = (bm >> 7) & 3;
            g_part[(size_t)(b * PNUM + p) * 4 + quarter] =
                make_float4(v, __int_as_float(k), qv, __int_as_float(qk));
        }
    }
}

// ---------------------------------------------------------------------------
// Kernel 3: selection — one warp per (b,p). it-0 from partials; the chain is
// then confined to rows [t0-3, t0+21] (each later pick moves <= +3, it-1
// moves <= ±3), so cache those 25 rows (800 B, contiguous) in smem. Rare
// fallback jumps outside -> per-iteration in_cache check reads global.
// ---------------------------------------------------------------------------
__global__ void __launch_bounds__(256)
select_kernel(const float* __restrict__ ps, float* __restrict__ out) {
    int tid = (int)threadIdx.x;
    int wid = tid >> 5, lane = tid & 31;
    int bp = blockIdx.x * 8 + wid;
    int p = bp % PNUM;
    const float* gd = g_dist + ((size_t)bp << 12);
    __shared__ float cache[8][25 * NPS];

    float fv = -INFINITY, fqv = -INFINITY;
    int fk = 0x7fffffff, fqk = 0x7fffffff;
    if (lane < 4) {
        float4 pr = g_part[(size_t)bp * 4 + lane];
        fv = pr.x; fk = __float_as_int(pr.y);
        fqv = pr.z; fqk = __float_as_int(pr.w);
    }
    #pragma unroll
    for (int o = 2; o; o >>= 1) {
        float ov = __shfl_xor_sync(0xffffffffu, fv, o);
        int   ok = __shfl_xor_sync(0xffffffffu, fk, o);
        amax_upd(fv, fk, ov, ok);
        float oqv = __shfl_xor_sync(0xffffffffu, fqv, o);
        int   oqk = __shfl_xor_sync(0xffffffffu, fqk, o);
        amax_upd(fqv, fqk, oqv, oqk);
    }
    fv  = __shfl_sync(0xffffffffu, fv, 0);
    fk  = __shfl_sync(0xffffffffu, fk, 0);
    fqv = __shfl_sync(0xffffffffu, fqv, 0);
    fqk = __shfl_sync(0xffffffffu, fqk, 0);

    float rv[NPS]; int re[NPS], rs[NPS];
    rv[0] = fv; re[0] = fk & (TLEN - 1); rs[0] = fk >> 9;
    int msub = 0xFF & ~(1 << rs[0]);
    int pe = re[0];

    // cache the reachable rows [lo, hi]
    int lo = max(re[0] - 3, 0);
    int hi = min(re[0] + 21, TLEN - 1);
    {
        int nvals = (hi - lo + 1) * NPS;
        const float* src = gd + (lo << 3);
        for (int q = lane; q < nvals; q += 32) cache[wid][q] = src[q];
    }
    __syncwarp();

    #pragma unroll
    for (int it = 1; it < NPS; it++) {
        int wlo = (it == 1) ? max(pe - 3, 0) : (pe + 1);
        int whi = min(pe + 3, TLEN - 1);
        int cnt = (whi >= wlo) ? (whi - wlo + 1) * NPS : 0;
        bool inc = (wlo >= lo) && (whi <= hi);
        float bv = -INFINITY;
        int   bk = 0x7fffffff;
        #pragma unroll
        for (int qq = 0; qq < 2; qq++) {
            int q = lane + qq * 32;
            if (q < cnt) {
                int t = wlo + (q >> 3), i = q & 7;
                bool ok2 = (msub >> i) & 1;
                #pragma unroll
                for (int j = 0; j < NPS - 1; j++)
                    if (j < it && re[j] == t) ok2 = false;
                if (ok2) {
                    float v = inc ? cache[wid][((t - lo) << 3) + i]
                                  : gd[(t << 3) + i];
                    amax_upd(bv, bk, v, (i << 9) | t);
                }
            }
        }
        #pragma unroll
        for (int o = 16; o; o >>= 1) {
            float ov = __shfl_xor_sync(0xffffffffu, bv, o);
            int   ok = __shfl_xor_sync(0xffffffffu, bk, o);
            amax_upd(bv, bk, ov, ok);
        }
        float recv;
        if (bk == 0x7fffffff) { bk = fqk; recv = fqv; }
        else                  recv = bv;
        int tt = bk & (TLEN - 1), ii = bk >> 9;
        rv[it] = recv; re[it] = tt; rs[it] = ii;
        msub &= ~(1 << ii);
        pe = tt;
    }

    if (lane == 0) {
        int ord[NPS];
        #pragma unroll
        for (int j = 0; j < NPS; j++) ord[j] = j;
        for (int a = 1; a < NPS; a++) {
            int o = ord[a], key = rs[o], bb = a - 1;
            while (bb >= 0 && rs[ord[bb]] > key) { ord[bb + 1] = ord[bb]; bb--; }
            ord[bb + 1] = o;
        }
        const float* pp = ps + (size_t)p * NPS;
        float slots[NPS];
        float factor = 0.0f;
        #pragma unroll
        for (int j = 0; j < NPS; j++) {
            float s = 1.0f / (1.0f + expf(-pp[j]));
            slots[j] = s; factor += s;
        }
        factor += 1e-10f;
        float acc = 0.0f;
        #pragma unroll
        for (int j = 0; j < NPS; j++)
            acc += rv[ord[j]] * (slots[j] * (float)NPS / factor);
        out[bp] = acc;
        out[BATCH * PNUM + bp] = (float)NPS - acc;
        #pragma unroll
        for (int j = 0; j < NPS; j++)
            out[2 * BATCH * PNUM + bp * NPS + j] = (float)re[ord[j]];
    }
}

// ---------------------------------------------------------------------------
extern "C" void kernel_launch(void* const* d_in, const int* in_sizes, int n_in,
                              void* d_out, int out_size) {
    (void)in_sizes; (void)n_in; (void)out_size;
    const float* x     = (const float*)d_in[0];
    const float* tmask = (const float*)d_in[1];
    const float* proto = (const float*)d_in[2];
    const float* psel  = (const float*)d_in[3];
    float* out = (float*)d_out;

    cudaFuncSetAttribute(gemm_mma_kernel,
                         cudaFuncAttributeMaxDynamicSharedMemorySize, GEMM_SMEM);

    split_all_kernel<<<MDIM + NPAD / NPS, 256>>>(x, proto);
    gemm_mma_kernel<<<dim3(NPAD / BN, MDIM / BM), 256, GEMM_SMEM>>>(tmask);
    select_kernel<<<BATCH * PNUM / 8, 256>>>(psel, out);
}

// round 13
// speedup vs baseline: 1.1571x; 1.0345x over previous
#include <cuda_runtime.h>
#include <cuda_fp16.h>
#include <math.h>
#include <cstdint>

#define BATCH 32
#define TLEN  512
#define DDIM  512
#define PNUM  200
#define NPS   8
#define MDIM  (BATCH*TLEN)   // 16384
#define NDIM  (PNUM*NPS)     // 1600
#define NPAD  1664           // 13 * 128 (GEMM N padding; pad cols never stored)
#define NEGC  (-100000.0f)
#define SCALE 2048.0f        // 2^11 operand prescale (keeps fp16 residuals normal)
#define INVSC (1.0f/(SCALE*SCALE))   // 2^-22, exact

// ---- scratch (static device globals; allocation-free per harness rules) ----
__device__ float g_dist[(size_t)BATCH * PNUM * TLEN * NPS];   // [bp][t*8+i], 105 MB
__device__ float4 g_part[(size_t)BATCH * PNUM * 4];           // per-quarter argmax partials
__device__ __half g_Ah[(size_t)MDIM * DDIM];                  // 16 MB
__device__ __half g_Al[(size_t)MDIM * DDIM];                  // 16 MB
__device__ __half g_Bh[(size_t)NPAD * DDIM];                  // 1.6 MB
__device__ __half g_Bl[(size_t)NPAD * DDIM];                  // 1.6 MB

#define XBLKS (MDIM / 8)     // 2048 x-split blocks (8 rows each)

// ---------------------------------------------------------------------------
// Kernel 1 (merged): blocks [0, XBLKS) split x rows warp-per-row;
// blocks [XBLKS, XBLKS+208) split prototypes (or zero pad rows).
// ---------------------------------------------------------------------------
__global__ void __launch_bounds__(256)
split_all_kernel(const float* __restrict__ x, const float* __restrict__ proto) {
    int blk = blockIdx.x;
    int tid = (int)threadIdx.x;

    if (blk < XBLKS) {
        // ---- x row split: warp-per-row, lane owns 16 contiguous floats ----
        int wid = tid >> 5, lane = tid & 31;
        int m = blk * 8 + wid;
        const float4* row = (const float4*)(x + (size_t)m * DDIM) + lane * 4;
        float4 v0 = row[0], v1 = row[1], v2 = row[2], v3 = row[3];
        float xv[16] = {v0.x, v0.y, v0.z, v0.w, v1.x, v1.y, v1.z, v1.w,
                        v2.x, v2.y, v2.z, v2.w, v3.x, v3.y, v3.z, v3.w};
        float s = 0.0f;
        #pragma unroll
        for (int j = 0; j < 16; j++) s += xv[j] * xv[j];
        #pragma unroll
        for (int o = 16; o; o >>= 1) s += __shfl_xor_sync(0xffffffffu, s, o);
        float inv = (1.0f / fmaxf(sqrtf(s), 1e-12f)) * SCALE;

        __half2 oh[8], ol[8];
        #pragma unroll
        for (int j = 0; j < 8; j++) {
            float a = xv[2 * j] * inv, b = xv[2 * j + 1] * inv;
            __half ha = __float2half(a);
            __half la = __float2half(a - __half2float(ha));
            __half hb = __float2half(b);
            __half lb = __float2half(b - __half2float(hb));
            oh[j] = __half2(ha, hb);
            ol[j] = __half2(la, lb);
        }
        size_t off = (size_t)m * DDIM + lane * 16;
        *(uint4*)(g_Ah + off)     = *(uint4*)&oh[0];
        *(uint4*)(g_Ah + off + 8) = *(uint4*)&oh[4];
        *(uint4*)(g_Al + off)     = *(uint4*)&ol[0];
        *(uint4*)(g_Al + off + 8) = *(uint4*)&ol[4];
        return;
    }

    // ---- prototype split ----
    int p = blk - XBLKS;
    if (p >= PNUM) {   // zero pad rows
        size_t base = (size_t)p * NPS * DDIM;
        __half2 z(__half(0.f), __half(0.f));
        for (int idx = tid; idx < NPS * DDIM / 2; idx += 256) {
            ((__half2*)(g_Bh + base))[idx] = z;
            ((__half2*)(g_Bl + base))[idx] = z;
        }
        return;
    }
    __shared__ float sp[DDIM * NPS];   // 16 KB
    __shared__ float sinvp[NPS];
    const float* base = proto + (size_t)p * DDIM * NPS;
    for (int idx = tid; idx < DDIM * NPS; idx += 256) sp[idx] = base[idx];
    __syncthreads();
    int w = tid >> 5, lane = tid & 31;
    if (w < NPS) {
        float s = 0.0f;
        for (int d = lane; d < DDIM; d += 32) { float v = sp[d*NPS + w]; s += v*v; }
        #pragma unroll
        for (int o = 16; o; o >>= 1) s += __shfl_down_sync(0xffffffffu, s, o);
        if (lane == 0) sinvp[w] = 1.0f / fmaxf(sqrtf(s), 1e-12f);
    }
    __syncthreads();
    for (int idx = tid; idx < NPS * DDIM; idx += 256) {
        int i = idx >> 9, d = idx & (DDIM - 1);
        float v = sp[d * NPS + i] * sinvp[i] * SCALE;
        __half h = __float2half(v);
        float r = v - __half2float(h);
        __half l = __float2half(r);
        size_t off = (size_t)(p * NPS + i) * DDIM + d;
        g_Bh[off] = h;
        g_Bl[off] = l;
    }
}

// ---------------------------------------------------------------------------
// Kernel 2: fp16 GEMM via mma.sync, 3 combos (hh, hl, lh). CTA 128x128,
// BK=32, 3-stage ring, ONE __syncthreads per mainloop iteration.
// 96 KB smem -> 2 CTAs/SM. Epilogue emits per-(b,p) per-quarter partials.
// ---------------------------------------------------------------------------
#define BM 128
#define BN 128
#define BK 32
#define KITERS (DDIM / BK)            // 16
#define BUF_BYTES (BM * BK * 2)       // 8192 per buffer
#define NSTAGE 3
#define GEMM_SMEM (NSTAGE * 4 * BUF_BYTES)  // 98304

__device__ __forceinline__ uint32_t smem_to_u32(const void* p) {
    uint32_t a;
    asm("{ .reg .u64 t; cvta.to.shared.u64 t, %1; cvt.u32.u64 %0, t; }"
        : "=r"(a) : "l"(p));
    return a;
}
#define CP_ASYNC16(saddr, gptr) \
    asm volatile("cp.async.cg.shared.global [%0], [%1], 16;" \
        :: "r"((uint32_t)(saddr)), "l"(gptr))
#define CP_COMMIT() asm volatile("cp.async.commit_group;" ::: "memory")
#define CP_WAIT(n)  asm volatile("cp.async.wait_group %0;" :: "n"(n) : "memory")

// 64B-row swizzle: conflict-free for 8-row ldmatrix access
__device__ __forceinline__ uint32_t swz64(int row, int ch) {
    return (uint32_t)(row * 64 + ((ch ^ ((row >> 1) & 3)) << 4));
}

__device__ __forceinline__ void ldsm_x4(uint32_t (&r)[4], uint32_t addr) {
    asm volatile("ldmatrix.sync.aligned.m8n8.x4.shared.b16 {%0,%1,%2,%3}, [%4];"
        : "=r"(r[0]), "=r"(r[1]), "=r"(r[2]), "=r"(r[3]) : "r"(addr));
}
__device__ __forceinline__ void mma16816(float (&d)[4], const uint32_t (&a)[4],
                                         uint32_t b0, uint32_t b1) {
    asm volatile(
        "mma.sync.aligned.m16n8k16.row.col.f32.f16.f16.f32 "
        "{%0,%1,%2,%3}, {%4,%5,%6,%7}, {%8,%9}, {%0,%1,%2,%3};"
        : "+f"(d[0]), "+f"(d[1]), "+f"(d[2]), "+f"(d[3])
        : "r"(a[0]), "r"(a[1]), "r"(a[2]), "r"(a[3]), "r"(b0), "r"(b1));
}
__device__ __forceinline__ void amax_upd(float& bv, int& bk, float v, int k) {
    if (v > bv || (v == bv && k < bk)) { bv = v; bk = k; }
}

__global__ void __launch_bounds__(256, 2)
gemm_mma_kernel(const float* __restrict__ tmask) {
    extern __shared__ __align__(128) char smem[];
    uint32_t sb = smem_to_u32(smem);

    int tid = (int)threadIdx.x;
    int wid = tid >> 5, lane = tid & 31;
    int bm = blockIdx.y * BM, bn = blockIdx.x * BN;
    int wm = (wid >> 2) * 64;       // warp m offset: 0 / 64
    int wn = (wid & 3) * 32;        // warp n offset: 0/32/64/96

    auto buf = [&](int s, int w) -> uint32_t {
        return sb + (uint32_t)(s * 4 + w) * BUF_BYTES;
    };

    const __half* gsrc[4] = {g_Ah + (size_t)bm * DDIM, g_Al + (size_t)bm * DDIM,
                             g_Bh + (size_t)bn * DDIM, g_Bl + (size_t)bn * DDIM};

    auto load_stage = [&](int kc, int s) {
        #pragma unroll
        for (int w = 0; w < 4; w++) {
            const __half* g = gsrc[w] + kc * BK;
            uint32_t sbase = buf(s, w);
            #pragma unroll
            for (int q = 0; q < 2; q++) {
                int idx = tid + q * 256;
                int row = idx >> 2, ch = idx & 3;
                CP_ASYNC16(sbase + swz64(row, ch), g + (size_t)row * DDIM + ch * 8);
            }
        }
    };

    float d[4][4][4];
    #pragma unroll
    for (int i = 0; i < 4; i++)
        #pragma unroll
        for (int j = 0; j < 4; j++)
            #pragma unroll
            for (int q = 0; q < 4; q++) d[i][j][q] = 0.0f;

    // prologue: NSTAGE-1 stages in flight
    load_stage(0, 0); CP_COMMIT();
    load_stage(1, 1); CP_COMMIT();
    CP_WAIT(1);
    __syncthreads();

    int s = 0;
    for (int kc = 0; kc < KITERS; kc++) {
        uint32_t aHb = buf(s, 0), aLb = buf(s, 1), bHb = buf(s, 2), bLb = buf(s, 3);
        #pragma unroll
        for (int ks = 0; ks < 2; ks++) {
            uint32_t ah[4][4], al[4][4];
            #pragma unroll
            for (int fm = 0; fm < 4; fm++) {
                int r = wm + fm * 16 + (lane & 15);
                int c = ks * 2 + (lane >> 4);
                uint32_t so = swz64(r, c);
                ldsm_x4(ah[fm], aHb + so);
                ldsm_x4(al[fm], aLb + so);
            }
            uint32_t bh[2][4], bl[2][4];
            #pragma unroll
            for (int g = 0; g < 2; g++) {
                int r = wn + g * 16 + (lane & 7) + ((lane >> 4) << 3);
                int c = ks * 2 + ((lane >> 3) & 1);
                uint32_t so = swz64(r, c);
                ldsm_x4(bh[g], bHb + so);
                ldsm_x4(bl[g], bLb + so);
            }
            #pragma unroll
            for (int fm = 0; fm < 4; fm++)
                #pragma unroll
                for (int fn = 0; fn < 4; fn++) {
                    uint32_t bh0 = bh[fn >> 1][(fn & 1) * 2];
                    uint32_t bh1 = bh[fn >> 1][(fn & 1) * 2 + 1];
                    uint32_t bl0 = bl[fn >> 1][(fn & 1) * 2];
                    uint32_t bl1 = bl[fn >> 1][(fn & 1) * 2 + 1];
                    mma16816(d[fm][fn], ah[fm], bh0, bh1);   // hh
                    mma16816(d[fm][fn], ah[fm], bl0, bl1);   // hl
                    mma16816(d[fm][fn], al[fm], bh0, bh1);   // lh
                }
        }
        // load stage (kc+2): its last readers finished before the sync that
        // ended iteration kc-1, so no extra barrier is needed here.
        int nk = kc + NSTAGE - 1;
        if (nk < KITERS) load_stage(nk, nk % NSTAGE);
        CP_COMMIT();   // empty groups at the tail keep wait-depth constant
        CP_WAIT(1);    // stage for kc+1 resident
        __syncthreads();
        s = (s == NSTAGE - 1) ? 0 : s + 1;
    }

    // ---- epilogue: store dist + per-fn (=per-p) argmax partials ----
    int gid = lane >> 2, tig = lane & 3;
    float pv[4], pqv[4]; int pk[4], pqk[4];
    #pragma unroll
    for (int fn = 0; fn < 4; fn++) {
        pv[fn] = -INFINITY; pqv[fn] = -INFINITY;
        pk[fn] = 0x7fffffff; pqk[fn] = 0x7fffffff;
    }

    #pragma unroll
    for (int fm = 0; fm < 4; fm++) {
        int m0 = bm + wm + fm * 16 + gid;
        int m1 = m0 + 8;
        int b = m0 >> 9;              // same for m0, m1
        int t0 = m0 & (TLEN - 1), t1 = m1 & (TLEN - 1);
        float tm0 = tmask[m0], tm1 = tmask[m1];
        float s0 = INVSC * tm0, s1 = INVSC * tm1;
        float na0 = (1.0f - tm0) * NEGC, na1 = (1.0f - tm1) * NEGC;
        #pragma unroll
        for (int fn = 0; fn < 4; fn++) {
            int n = bn + wn + fn * 8 + tig * 2;
            if (n >= NDIM) continue;
            int p = n >> 3, i = n & 7;
            size_t base = ((size_t)(b * PNUM + p) << 12);
            float2 o0, o1;
            o0.x = d[fm][fn][0] * s0 + na0;
            o0.y = d[fm][fn][1] * s0 + na0;
            o1.x = d[fm][fn][2] * s1 + na1;
            o1.y = d[fm][fn][3] * s1 + na1;
            *(float2*)(g_dist + base + (t0 << 3) + i) = o0;
            *(float2*)(g_dist + base + (t1 << 3) + i) = o1;
            int k00 = (i << 9) | t0, k01 = ((i + 1) << 9) | t0;
            int k10 = (i << 9) | t1, k11 = ((i + 1) << 9) | t1;
            amax_upd(pv[fn], pk[fn], o0.x, k00);
            amax_upd(pv[fn], pk[fn], o0.y, k01);
            amax_upd(pv[fn], pk[fn], o1.x, k10);
            amax_upd(pv[fn], pk[fn], o1.y, k11);
            amax_upd(pqv[fn], pqk[fn], o0.x + NEGC, k00);
            amax_upd(pqv[fn], pqk[fn], o0.y + NEGC, k01);
            amax_upd(pqv[fn], pqk[fn], o1.x + NEGC, k10);
            amax_upd(pqv[fn], pqk[fn], o1.y + NEGC, k11);
        }
    }

    float4* sm_part = (float4*)smem;   // 32 entries, reuses stage buffers
    __syncthreads();                   // mainloop smem reads fully done
    #pragma unroll
    for (int fn = 0; fn < 4; fn++) {
        float v = pv[fn], qv = pqv[fn];
        int k = pk[fn], qk = pqk[fn];
        #pragma unroll
        for (int o = 16; o; o >>= 1) {
            float ov = __shfl_xor_sync(0xffffffffu, v, o);
            int   ok = __shfl_xor_sync(0xffffffffu, k, o);
            amax_upd(v, k, ov, ok);
            float oqv = __shfl_xor_sync(0xffffffffu, qv, o);
            int   oqk = __shfl_xor_sync(0xffffffffu, qk, o);
            amax_upd(qv, qk, oqv, oqk);
        }
        if (lane == 0)
            sm_part[wid * 4 + fn] =
                make_float4(v, __int_as_float(k), qv, __int_as_float(qk));
    }
    __syncthreads();
    if (tid < 16) {
        int wn_i = tid >> 2, fn = tid & 3;
        float4 a = sm_part[wn_i * 4 + fn];          // warp row 0 (wm=0)
        float4 c = sm_part[(4 + wn_i) * 4 + fn];    // warp row 1 (wm=64)
        float v = a.x; int k = __float_as_int(a.y);
        float qv = a.z; int qk = __float_as_int(a.w);
        amax_upd(v, k, c.x, __float_as_int(c.y));
        amax_upd(qv, qk, c.z, __float_as_int(c.w));
        int n0 = bn + wn_i * 32 + fn * 8;
        int p = n0 >> 3;
        if (p < PNUM) {
            int b = bm >> 9;
            int quarter = (bm >> 7) & 3;
            g_part[(size_t)(b * PNUM + p) * 4 + quarter] =
                make_float4(v, __int_as_float(k), qv, __int_as_float(qk));
        }
    }
}

// ---------------------------------------------------------------------------
// Kernel 3: selection — one warp per (b,p). it-0 from partials; the chain is
// then confined to rows [t0-3, t0+21], cached in smem (800 B contiguous).
// Rare fallback jumps outside -> per-iteration in_cache check reads global.
// ---------------------------------------------------------------------------
__global__ void __launch_bounds__(256)
select_kernel(const float* __restrict__ ps, float* __restrict__ out) {
    int tid = (int)threadIdx.x;
    int wid = tid >> 5, lane = tid & 31;
    int bp = blockIdx.x * 8 + wid;
    int p = bp % PNUM;
    const float* gd = g_dist + ((size_t)bp << 12);
    __shared__ float cache[8][25 * NPS];

    float fv = -INFINITY, fqv = -INFINITY;
    int fk = 0x7fffffff, fqk = 0x7fffffff;
    if (lane < 4) {
        float4 pr = g_part[(size_t)bp * 4 + lane];
        fv = pr.x; fk = __float_as_int(pr.y);
        fqv = pr.z; fqk = __float_as_int(pr.w);
    }
    #pragma unroll
    for (int o = 2; o; o >>= 1) {
        float ov = __shfl_xor_sync(0xffffffffu, fv, o);
        int   ok = __shfl_xor_sync(0xffffffffu, fk, o);
        amax_upd(fv, fk, ov, ok);
        float oqv = __shfl_xor_sync(0xffffffffu, fqv, o);
        int   oqk = __shfl_xor_sync(0xffffffffu, fqk, o);
        amax_upd(fqv, fqk, oqv, oqk);
    }
    fv  = __shfl_sync(0xffffffffu, fv, 0);
    fk  = __shfl_sync(0xffffffffu, fk, 0);
    fqv = __shfl_sync(0xffffffffu, fqv, 0);
    fqk = __shfl_sync(0xffffffffu, fqk, 0);

    float rv[NPS]; int re[NPS], rs[NPS];
    rv[0] = fv; re[0] = fk & (TLEN - 1); rs[0] = fk >> 9;
    int msub = 0xFF & ~(1 << rs[0]);
    int pe = re[0];

    // cache the reachable rows [lo, hi]
    int lo = max(re[0] - 3, 0);
    int hi = min(re[0] + 21, TLEN - 1);
    {
        int nvals = (hi - lo + 1) * NPS;
        const float* src = gd + (lo << 3);
        for (int q = lane; q < nvals; q += 32) cache[wid][q] = src[q];
    }
    __syncwarp();

    #pragma unroll
    for (int it = 1; it < NPS; it++) {
        int wlo = (it == 1) ? max(pe - 3, 0) : (pe + 1);
        int whi = min(pe + 3, TLEN - 1);
        int cnt = (whi >= wlo) ? (whi - wlo + 1) * NPS : 0;
        bool inc = (wlo >= lo) && (whi <= hi);
        float bv = -INFINITY;
        int   bk = 0x7fffffff;
        #pragma unroll
        for (int qq = 0; qq < 2; qq++) {
            int q = lane + qq * 32;
            if (q < cnt) {
                int t = wlo + (q >> 3), i = q & 7;
                bool ok2 = (msub >> i) & 1;
                #pragma unroll
                for (int j = 0; j < NPS - 1; j++)
                    if (j < it && re[j] == t) ok2 = false;
                if (ok2) {
                    float v = inc ? cache[wid][((t - lo) << 3) + i]
                                  : gd[(t << 3) + i];
                    amax_upd(bv, bk, v, (i << 9) | t);
                }
            }
        }
        #pragma unroll
        for (int o = 16; o; o >>= 1) {
            float ov = __shfl_xor_sync(0xffffffffu, bv, o);
            int   ok = __shfl_xor_sync(0xffffffffu, bk, o);
            amax_upd(bv, bk, ov, ok);
        }
        float recv;
        if (bk == 0x7fffffff) { bk = fqk; recv = fqv; }
        else                  recv = bv;
        int tt = bk & (TLEN - 1), ii = bk >> 9;
        rv[it] = recv; re[it] = tt; rs[it] = ii;
        msub &= ~(1 << ii);
        pe = tt;
    }

    if (lane == 0) {
        int ord[NPS];
        #pragma unroll
        for (int j = 0; j < NPS; j++) ord[j] = j;
        for (int a = 1; a < NPS; a++) {
            int o = ord[a], key = rs[o], bb = a - 1;
            while (bb >= 0 && rs[ord[bb]] > key) { ord[bb + 1] = ord[bb]; bb--; }
            ord[bb + 1] = o;
        }
        const float* pp = ps + (size_t)p * NPS;
        float slots[NPS];
        float factor = 0.0f;
        #pragma unroll
        for (int j = 0; j < NPS; j++) {
            float s = 1.0f / (1.0f + expf(-pp[j]));
            slots[j] = s; factor += s;
        }
        factor += 1e-10f;
        float acc = 0.0f;
        #pragma unroll
        for (int j = 0; j < NPS; j++)
            acc += rv[ord[j]] * (slots[j] * (float)NPS / factor);
        out[bp] = acc;
        out[BATCH * PNUM + bp] = (float)NPS - acc;
        #pragma unroll
        for (int j = 0; j < NPS; j++)
            out[2 * BATCH * PNUM + bp * NPS + j] = (float)re[ord[j]];
    }
}

// ---------------------------------------------------------------------------
extern "C" void kernel_launch(void* const* d_in, const int* in_sizes, int n_in,
                              void* d_out, int out_size) {
    (void)in_sizes; (void)n_in; (void)out_size;
    const float* x     = (const float*)d_in[0];
    const float* tmask = (const float*)d_in[1];
    const float* proto = (const float*)d_in[2];
    const float* psel  = (const float*)d_in[3];
    float* out = (float*)d_out;

    cudaFuncSetAttribute(gemm_mma_kernel,
                         cudaFuncAttributeMaxDynamicSharedMemorySize, GEMM_SMEM);

    split_all_kernel<<<XBLKS + NPAD / NPS, 256>>>(x, proto);
    gemm_mma_kernel<<<dim3(NPAD / BN, MDIM / BM), 256, GEMM_SMEM>>>(tmask);
    select_kernel<<<BATCH * PNUM / 8, 256>>>(psel, out);
}

// round 15
// speedup vs baseline: 1.1607x; 1.0031x over previous
#include <cuda_runtime.h>
#include <cuda_fp16.h>
#include <math.h>
#include <cstdint>

#define BATCH 32
#define TLEN  512
#define DDIM  512
#define PNUM  200
#define NPS   8
#define MDIM  (BATCH*TLEN)   // 16384
#define NDIM  (PNUM*NPS)     // 1600
#define NPAD  1664           // 13 * 128 (GEMM N padding; pad cols never stored)
#define NEGC  (-100000.0f)
#define SCALE 2048.0f        // 2^11 operand prescale (keeps fp16 residuals normal)
#define INVSC (1.0f/(SCALE*SCALE))   // 2^-22, exact

// ---- scratch (static device globals; allocation-free per harness rules) ----
__device__ float g_dist[(size_t)BATCH * PNUM * TLEN * NPS];   // [bp][t*8+i], 105 MB
__device__ float4 g_part[(size_t)BATCH * PNUM * 4];           // per-quarter argmax partials
__device__ __half g_Ah[(size_t)MDIM * DDIM];                  // 16 MB
__device__ __half g_Al[(size_t)MDIM * DDIM];                  // 16 MB
__device__ __half g_Bh[(size_t)NPAD * DDIM];                  // 1.6 MB
__device__ __half g_Bl[(size_t)NPAD * DDIM];                  // 1.6 MB

#define XBLKS (MDIM / 16)    // 1024 x-split blocks (16 rows each, 2 rows/warp)

// ---------------------------------------------------------------------------
// Kernel 1 (merged): blocks [0, XBLKS) split x rows (2 rows per warp, ILP-2,
// lane owns 16 contiguous floats per row — full 512 coverage per row);
// blocks [XBLKS, XBLKS+208) split prototypes (or zero pad rows).
// ---------------------------------------------------------------------------
__global__ void __launch_bounds__(256)
split_all_kernel(const float* __restrict__ x, const float* __restrict__ proto) {
    int blk = blockIdx.x;
    int tid = (int)threadIdx.x;

    if (blk < XBLKS) {
        int wid = tid >> 5, lane = tid & 31;
        int m0 = blk * 16 + wid * 2;
        int m1 = m0 + 1;
        // lane owns floats [lane*16, lane*16+16) of each row: 4 float4 per row
        const float4* r0 = (const float4*)(x + (size_t)m0 * DDIM) + lane * 4;
        const float4* r1 = (const float4*)(x + (size_t)m1 * DDIM) + lane * 4;
        float4 a0 = r0[0], a1 = r0[1], a2 = r0[2], a3 = r0[3];
        float4 b0 = r1[0], b1 = r1[1], b2 = r1[2], b3 = r1[3];
        float xa[16] = {a0.x, a0.y, a0.z, a0.w, a1.x, a1.y, a1.z, a1.w,
                        a2.x, a2.y, a2.z, a2.w, a3.x, a3.y, a3.z, a3.w};
        float xb[16] = {b0.x, b0.y, b0.z, b0.w, b1.x, b1.y, b1.z, b1.w,
                        b2.x, b2.y, b2.z, b2.w, b3.x, b3.y, b3.z, b3.w};
        float s0 = 0.0f, s1 = 0.0f;
        #pragma unroll
        for (int j = 0; j < 16; j++) { s0 += xa[j] * xa[j]; s1 += xb[j] * xb[j]; }
        #pragma unroll
        for (int o = 16; o; o >>= 1) {
            s0 += __shfl_xor_sync(0xffffffffu, s0, o);
            s1 += __shfl_xor_sync(0xffffffffu, s1, o);
        }
        float inv0 = (1.0f / fmaxf(sqrtf(s0), 1e-12f)) * SCALE;
        float inv1 = (1.0f / fmaxf(sqrtf(s1), 1e-12f)) * SCALE;

        __half2 h0[8], l0[8], h1[8], l1[8];
        #pragma unroll
        for (int j = 0; j < 8; j++) {
            float pa = xa[2 * j] * inv0, pb = xa[2 * j + 1] * inv0;
            __half ha = __float2half(pa);
            __half la = __float2half(pa - __half2float(ha));
            __half hb = __float2half(pb);
            __half lb = __float2half(pb - __half2float(hb));
            h0[j] = __half2(ha, hb); l0[j] = __half2(la, lb);
            float qa = xb[2 * j] * inv1, qb = xb[2 * j + 1] * inv1;
            __half hc = __float2half(qa);
            __half lc = __float2half(qa - __half2float(hc));
            __half hd = __float2half(qb);
            __half ld = __float2half(qb - __half2float(hd));
            h1[j] = __half2(hc, hd); l1[j] = __half2(lc, ld);
        }
        size_t off0 = (size_t)m0 * DDIM + lane * 16;
        size_t off1 = (size_t)m1 * DDIM + lane * 16;
        *(uint4*)(g_Ah + off0)     = *(uint4*)&h0[0];
        *(uint4*)(g_Ah + off0 + 8) = *(uint4*)&h0[4];
        *(uint4*)(g_Al + off0)     = *(uint4*)&l0[0];
        *(uint4*)(g_Al + off0 + 8) = *(uint4*)&l0[4];
        *(uint4*)(g_Ah + off1)     = *(uint4*)&h1[0];
        *(uint4*)(g_Ah + off1 + 8) = *(uint4*)&h1[4];
        *(uint4*)(g_Al + off1)     = *(uint4*)&l1[0];
        *(uint4*)(g_Al + off1 + 8) = *(uint4*)&l1[4];
        return;
    }

    // ---- prototype split ----
    int p = blk - XBLKS;
    if (p >= PNUM) {   // zero pad rows
        size_t base = (size_t)p * NPS * DDIM;
        __half2 z(__half(0.f), __half(0.f));
        for (int idx = tid; idx < NPS * DDIM / 2; idx += 256) {
            ((__half2*)(g_Bh + base))[idx] = z;
            ((__half2*)(g_Bl + base))[idx] = z;
        }
        return;
    }
    __shared__ float sp[DDIM * NPS];   // 16 KB
    __shared__ float sinvp[NPS];
    const float* base = proto + (size_t)p * DDIM * NPS;
    for (int idx = tid; idx < DDIM * NPS; idx += 256) sp[idx] = base[idx];
    __syncthreads();
    int w = tid >> 5, lane = tid & 31;
    if (w < NPS) {
        float s = 0.0f;
        for (int d = lane; d < DDIM; d += 32) { float v = sp[d*NPS + w]; s += v*v; }
        #pragma unroll
        for (int o = 16; o; o >>= 1) s += __shfl_down_sync(0xffffffffu, s, o);
        if (lane == 0) sinvp[w] = 1.0f / fmaxf(sqrtf(s), 1e-12f);
    }
    __syncthreads();
    for (int idx = tid; idx < NPS * DDIM; idx += 256) {
        int i = idx >> 9, d = idx & (DDIM - 1);
        float v = sp[d * NPS + i] * sinvp[i] * SCALE;
        __half h = __float2half(v);
        float r = v - __half2float(h);
        __half l = __float2half(r);
        size_t off = (size_t)(p * NPS + i) * DDIM + d;
        g_Bh[off] = h;
        g_Bl[off] = l;
    }
}

// ---------------------------------------------------------------------------
// Kernel 2: fp16 GEMM via mma.sync, 3 combos (hh, hl, lh). CTA 128x128,
// BK=32, 3-stage ring, ONE __syncthreads per mainloop iteration.
// 96 KB smem -> 2 CTAs/SM. Epilogue emits per-(b,p) per-quarter partials.
// ---------------------------------------------------------------------------
#define BM 128
#define BN 128
#define BK 32
#define KITERS (DDIM / BK)            // 16
#define BUF_BYTES (BM * BK * 2)       // 8192 per buffer
#define NSTAGE 3
#define GEMM_SMEM (NSTAGE * 4 * BUF_BYTES)  // 98304

__device__ __forceinline__ uint32_t smem_to_u32(const void* p) {
    uint32_t a;
    asm("{ .reg .u64 t; cvta.to.shared.u64 t, %1; cvt.u32.u64 %0, t; }"
        : "=r"(a) : "l"(p));
    return a;
}
#define CP_ASYNC16(saddr, gptr) \
    asm volatile("cp.async.cg.shared.global [%0], [%1], 16;" \
        :: "r"((uint32_t)(saddr)), "l"(gptr))
#define CP_COMMIT() asm volatile("cp.async.commit_group;" ::: "memory")
#define CP_WAIT(n)  asm volatile("cp.async.wait_group %0;" :: "n"(n) : "memory")

// 64B-row swizzle: conflict-free for 8-row ldmatrix access
__device__ __forceinline__ uint32_t swz64(int row, int ch) {
    return (uint32_t)(row * 64 + ((ch ^ ((row >> 1) & 3)) << 4));
}

__device__ __forceinline__ void ldsm_x4(uint32_t (&r)[4], uint32_t addr) {
    asm volatile("ldmatrix.sync.aligned.m8n8.x4.shared.b16 {%0,%1,%2,%3}, [%4];"
        : "=r"(r[0]), "=r"(r[1]), "=r"(r[2]), "=r"(r[3]) : "r"(addr));
}
__device__ __forceinline__ void mma16816(float (&d)[4], const uint32_t (&a)[4],
                                         uint32_t b0, uint32_t b1) {
    asm volatile(
        "mma.sync.aligned.m16n8k16.row.col.f32.f16.f16.f32 "
        "{%0,%1,%2,%3}, {%4,%5,%6,%7}, {%8,%9}, {%0,%1,%2,%3};"
        : "+f"(d[0]), "+f"(d[1]), "+f"(d[2]), "+f"(d[3])
        : "r"(a[0]), "r"(a[1]), "r"(a[2]), "r"(a[3]), "r"(b0), "r"(b1));
}
__device__ __forceinline__ void amax_upd(float& bv, int& bk, float v, int k) {
    if (v > bv || (v == bv && k < bk)) { bv = v; bk = k; }
}

__global__ void __launch_bounds__(256, 2)
gemm_mma_kernel(const float* __restrict__ tmask) {
    extern __shared__ __align__(128) char smem[];
    uint32_t sb = smem_to_u32(smem);

    int tid = (int)threadIdx.x;
    int wid = tid >> 5, lane = tid & 31;
    int bm = blockIdx.y * BM, bn = blockIdx.x * BN;
    int wm = (wid >> 2) * 64;       // warp m offset: 0 / 64
    int wn = (wid & 3) * 32;        // warp n offset: 0/32/64/96

    auto buf = [&](int s, int w) -> uint32_t {
        return sb + (uint32_t)(s * 4 + w) * BUF_BYTES;
    };

    const __half* gsrc[4] = {g_Ah + (size_t)bm * DDIM, g_Al + (size_t)bm * DDIM,
                             g_Bh + (size_t)bn * DDIM, g_Bl + (size_t)bn * DDIM};

    auto load_stage = [&](int kc, int s) {
        #pragma unroll
        for (int w = 0; w < 4; w++) {
            const __half* g = gsrc[w] + kc * BK;
            uint32_t sbase = buf(s, w);
            #pragma unroll
            for (int q = 0; q < 2; q++) {
                int idx = tid + q * 256;
                int row = idx >> 2, ch = idx & 3;
                CP_ASYNC16(sbase + swz64(row, ch), g + (size_t)row * DDIM + ch * 8);
            }
        }
    };

    float d[4][4][4];
    #pragma unroll
    for (int i = 0; i < 4; i++)
        #pragma unroll
        for (int j = 0; j < 4; j++)
            #pragma unroll
            for (int q = 0; q < 4; q++) d[i][j][q] = 0.0f;

    // prologue: NSTAGE-1 stages in flight
    load_stage(0, 0); CP_COMMIT();
    load_stage(1, 1); CP_COMMIT();
    CP_WAIT(1);
    __syncthreads();

    int s = 0;
    for (int kc = 0; kc < KITERS; kc++) {
        uint32_t aHb = buf(s, 0), aLb = buf(s, 1), bHb = buf(s, 2), bLb = buf(s, 3);
        #pragma unroll
        for (int ks = 0; ks < 2; ks++) {
            uint32_t ah[4][4], al[4][4];
            #pragma unroll
            for (int fm = 0; fm < 4; fm++) {
                int r = wm + fm * 16 + (lane & 15);
                int c = ks * 2 + (lane >> 4);
                uint32_t so = swz64(r, c);
                ldsm_x4(ah[fm], aHb + so);
                ldsm_x4(al[fm], aLb + so);
            }
            uint32_t bh[2][4], bl[2][4];
            #pragma unroll
            for (int g = 0; g < 2; g++) {
                int r = wn + g * 16 + (lane & 7) + ((lane >> 4) << 3);
                int c = ks * 2 + ((lane >> 3) & 1);
                uint32_t so = swz64(r, c);
                ldsm_x4(bh[g], bHb + so);
                ldsm_x4(bl[g], bLb + so);
            }
            #pragma unroll
            for (int fm = 0; fm < 4; fm++)
                #pragma unroll
                for (int fn = 0; fn < 4; fn++) {
                    uint32_t bh0 = bh[fn >> 1][(fn & 1) * 2];
                    uint32_t bh1 = bh[fn >> 1][(fn & 1) * 2 + 1];
                    uint32_t bl0 = bl[fn >> 1][(fn & 1) * 2];
                    uint32_t bl1 = bl[fn >> 1][(fn & 1) * 2 + 1];
                    mma16816(d[fm][fn], ah[fm], bh0, bh1);   // hh
                    mma16816(d[fm][fn], ah[fm], bl0, bl1);   // hl
                    mma16816(d[fm][fn], al[fm], bh0, bh1);   // lh
                }
        }
        // load stage (kc+2): its last readers finished before the sync that
        // ended iteration kc-1, so no extra barrier is needed here.
        int nk = kc + NSTAGE - 1;
        if (nk < KITERS) load_stage(nk, nk % NSTAGE);
        CP_COMMIT();   // empty groups at the tail keep wait-depth constant
        CP_WAIT(1);    // stage for kc+1 resident
        __syncthreads();
        s = (s == NSTAGE - 1) ? 0 : s + 1;
    }

    // ---- epilogue: store dist + per-fn (=per-p) argmax partials ----
    int gid = lane >> 2, tig = lane & 3;
    float pv[4], pqv[4]; int pk[4], pqk[4];
    #pragma unroll
    for (int fn = 0; fn < 4; fn++) {
        pv[fn] = -INFINITY; pqv[fn] = -INFINITY;
        pk[fn] = 0x7fffffff; pqk[fn] = 0x7fffffff;
    }

    #pragma unroll
    for (int fm = 0; fm < 4; fm++) {
        int m0 = bm + wm + fm * 16 + gid;
        int m1 = m0 + 8;
        int b = m0 >> 9;              // same for m0, m1
        int t0 = m0 & (TLEN - 1), t1 = m1 & (TLEN - 1);
        float tm0 = tmask[m0], tm1 = tmask[m1];
        float s0 = INVSC * tm0, s1 = INVSC * tm1;
        float na0 = (1.0f - tm0) * NEGC, na1 = (1.0f - tm1) * NEGC;
        #pragma unroll
        for (int fn = 0; fn < 4; fn++) {
            int n = bn + wn + fn * 8 + tig * 2;
            if (n >= NDIM) continue;
            int p = n >> 3, i = n & 7;
            size_t base = ((size_t)(b * PNUM + p) << 12);
            float2 o0, o1;
            o0.x = d[fm][fn][0] * s0 + na0;
            o0.y = d[fm][fn][1] * s0 + na0;
            o1.x = d[fm][fn][2] * s1 + na1;
            o1.y = d[fm][fn][3] * s1 + na1;
            *(float2*)(g_dist + base + (t0 << 3) + i) = o0;
            *(float2*)(g_dist + base + (t1 << 3) + i) = o1;
            int k00 = (i << 9) | t0, k01 = ((i + 1) << 9) | t0;
            int k10 = (i << 9) | t1, k11 = ((i + 1) << 9) | t1;
            amax_upd(pv[fn], pk[fn], o0.x, k00);
            amax_upd(pv[fn], pk[fn], o0.y, k01);
            amax_upd(pv[fn], pk[fn], o1.x, k10);
            amax_upd(pv[fn], pk[fn], o1.y, k11);
            amax_upd(pqv[fn], pqk[fn], o0.x + NEGC, k00);
            amax_upd(pqv[fn], pqk[fn], o0.y + NEGC, k01);
            amax_upd(pqv[fn], pqk[fn], o1.x + NEGC, k10);
            amax_upd(pqv[fn], pqk[fn], o1.y + NEGC, k11);
        }
    }

    float4* sm_part = (float4*)smem;   // 32 entries, reuses stage buffers
    __syncthreads();                   // mainloop smem reads fully done
    #pragma unroll
    for (int fn = 0; fn < 4; fn++) {
        float v = pv[fn], qv = pqv[fn];
        int k = pk[fn], qk = pqk[fn];
        #pragma unroll
        for (int o = 16; o; o >>= 1) {
            float ov = __shfl_xor_sync(0xffffffffu, v, o);
            int   ok = __shfl_xor_sync(0xffffffffu, k, o);
            amax_upd(v, k, ov, ok);
            float oqv = __shfl_xor_sync(0xffffffffu, qv, o);
            int   oqk = __shfl_xor_sync(0xffffffffu, qk, o);
            amax_upd(qv, qk, oqv, oqk);
        }
        if (lane == 0)
            sm_part[wid * 4 + fn] =
                make_float4(v, __int_as_float(k), qv, __int_as_float(qk));
    }
    __syncthreads();
    if (tid < 16) {
        int wn_i = tid >> 2, fn = tid & 3;
        float4 a = sm_part[wn_i * 4 + fn];          // warp row 0 (wm=0)
        float4 c = sm_part[(4 + wn_i) * 4 + fn];    // warp row 1 (wm=64)
        float v = a.x; int k = __float_as_int(a.y);
        float qv = a.z; int qk = __float_as_int(a.w);
        amax_upd(v, k, c.x, __float_as_int(c.y));
        amax_upd(qv, qk, c.z, __float_as_int(c.w));
        int n0 = bn + wn_i * 32 + fn * 8;
        int p = n0 >> 3;
        if (p < PNUM) {
            int b = bm >> 9;
            int quarter = (bm >> 7) & 3;
            g_part[(size_t)(b * PNUM + p) * 4 + quarter] =
                make_float4(v, __int_as_float(k), qv, __int_as_float(qk));
        }
    }
}

// ---------------------------------------------------------------------------
// Kernel 3: selection — one warp per (b,p). it-0 from partials; the chain is
// then confined to rows [t0-3, t0+21], cached in smem (800 B contiguous).
// Rare fallback jumps outside -> per-iteration in_cache check reads global.
// ---------------------------------------------------------------------------
__global__ void __launch_bounds__(256)
select_kernel(const float* __restrict__ ps, float* __restrict__ out) {
    int tid = (int)threadIdx.x;
    int wid = tid >> 5, lane = tid & 31;
    int bp = blockIdx.x * 8 + wid;
    int p = bp % PNUM;
    const float* gd = g_dist + ((size_t)bp << 12);
    __shared__ float cache[8][25 * NPS];

    float fv = -INFINITY, fqv = -INFINITY;
    int fk = 0x7fffffff, fqk = 0x7fffffff;
    if (lane < 4) {
        float4 pr = g_part[(size_t)bp * 4 + lane];
        fv = pr.x; fk = __float_as_int(pr.y);
        fqv = pr.z; fqk = __float_as_int(pr.w);
    }
    #pragma unroll
    for (int o = 2; o; o >>= 1) {
        float ov = __shfl_xor_sync(0xffffffffu, fv, o);
        int   ok = __shfl_xor_sync(0xffffffffu, fk, o);
        amax_upd(fv, fk, ov, ok);
        float oqv = __shfl_xor_sync(0xffffffffu, fqv, o);
        int   oqk = __shfl_xor_sync(0xffffffffu, fqk, o);
        amax_upd(fqv, fqk, oqv, oqk);
    }
    fv  = __shfl_sync(0xffffffffu, fv, 0);
    fk  = __shfl_sync(0xffffffffu, fk, 0);
    fqv = __shfl_sync(0xffffffffu, fqv, 0);
    fqk = __shfl_sync(0xffffffffu, fqk, 0);

    float rv[NPS]; int re[NPS], rs[NPS];
    rv[0] = fv; re[0] = fk & (TLEN - 1); rs[0] = fk >> 9;
    int msub = 0xFF & ~(1 << rs[0]);
    int pe = re[0];

    // cache the reachable rows [lo, hi]
    int lo = max(re[0] - 3, 0);
    int hi = min(re[0] + 21, TLEN - 1);
    {
        int nvals = (hi - lo + 1) * NPS;
        const float* src = gd + (lo << 3);
        for (int q = lane; q < nvals; q += 32) cache[wid][q] = src[q];
    }
    __syncwarp();

    #pragma unroll
    for (int it = 1; it < NPS; it++) {
        int wlo = (it == 1) ? max(pe - 3, 0) : (pe + 1);
        int whi = min(pe + 3, TLEN - 1);
        int cnt = (whi >= wlo) ? (whi - wlo + 1) * NPS : 0;
        bool inc = (wlo >= lo) && (whi <= hi);
        float bv = -INFINITY;
        int   bk = 0x7fffffff;
        #pragma unroll
        for (int qq = 0; qq < 2; qq++) {
            int q = lane + qq * 32;
            if (q < cnt) {
                int t = wlo + (q >> 3), i = q & 7;
                bool ok2 = (msub >> i) & 1;
                #pragma unroll
                for (int j = 0; j < NPS - 1; j++)
                    if (j < it && re[j] == t) ok2 = false;
                if (ok2) {
                    float v = inc ? cache[wid][((t - lo) << 3) + i]
                                  : gd[(t << 3) + i];
                    amax_upd(bv, bk, v, (i << 9) | t);
                }
            }
        }
        #pragma unroll
        for (int o = 16; o; o >>= 1) {
            float ov = __shfl_xor_sync(0xffffffffu, bv, o);
            int   ok = __shfl_xor_sync(0xffffffffu, bk, o);
            amax_upd(bv, bk, ov, ok);
        }
        float recv;
        if (bk == 0x7fffffff) { bk = fqk; recv = fqv; }
        else                  recv = bv;
        int tt = bk & (TLEN - 1), ii = bk >> 9;
        rv[it] = recv; re[it] = tt; rs[it] = ii;
        msub &= ~(1 << ii);
        pe = tt;
    }

    if (lane == 0) {
        int ord[NPS];
        #pragma unroll
        for (int j = 0; j < NPS; j++) ord[j] = j;
        for (int a = 1; a < NPS; a++) {
            int o = ord[a], key = rs[o], bb = a - 1;
            while (bb >= 0 && rs[ord[bb]] > key) { ord[bb + 1] = ord[bb]; bb--; }
            ord[bb + 1] = o;
        }
        const float* pp = ps + (size_t)p * NPS;
        float slots[NPS];
        float factor = 0.0f;
        #pragma unroll
        for (int j = 0; j < NPS; j++) {
            float s = 1.0f / (1.0f + expf(-pp[j]));
            slots[j] = s; factor += s;
        }
        factor += 1e-10f;
        float acc = 0.0f;
        #pragma unroll
        for (int j = 0; j < NPS; j++)
            acc += rv[ord[j]] * (slots[j] * (float)NPS / factor);
        out[bp] = acc;
        out[BATCH * PNUM + bp] = (float)NPS - acc;
        #pragma unroll
        for (int j = 0; j < NPS; j++)
            out[2 * BATCH * PNUM + bp * NPS + j] = (float)re[ord[j]];
    }
}

// ---------------------------------------------------------------------------
extern "C" void kernel_launch(void* const* d_in, const int* in_sizes, int n_in,
                              void* d_out, int out_size) {
    (void)in_sizes; (void)n_in; (void)out_size;
    const float* x     = (const float*)d_in[0];
    const float* tmask = (const float*)d_in[1];
    const float* proto = (const float*)d_in[2];
    const float* psel  = (const float*)d_in[3];
    float* out = (float*)d_out;

    cudaFuncSetAttribute(gemm_mma_kernel,
                         cudaFuncAttributeMaxDynamicSharedMemorySize, GEMM_SMEM);

    split_all_kernel<<<XBLKS + NPAD / NPS, 256>>>(x, proto);
    gemm_mma_kernel<<<dim3(NPAD / BN, MDIM / BM), 256, GEMM_SMEM>>>(tmask);
    select_kernel<<<BATCH * PNUM / 8, 256>>>(psel, out);
}